// round 2
// baseline (speedup 1.0000x reference)
#include <cuda_runtime.h>
#include <cuda_bf16.h>

// LSTM_discriminator: B=2048, T=512, H=128, input dim 1.
// inputs: 0:x[2048,512] 1:hx0[2048,128] 2:cx0[2048,128] 3:W_ih[512,1]
//         4:W_hh[512,128] 5:b_ih[512] 6:b_hh[512] 7:W_mlp[1,128] 8:b_mlp[1]
// output: sigmoid(h_T @ W_mlp^T + b_mlp) -> [2048,1] fp32

#define Bsz 2048
#define Tsz 512
#define Hsz 128
#define ROWS_PER_CTA 16
#define NCTA (Bsz / ROWS_PER_CTA)   // 128
#define NTHREADS 512

// Packed recurrent weights: g_Wp[k*128 + j] = {W_hh[j][k], W_hh[128+j][k], W_hh[256+j][k], W_hh[384+j][k]}
__device__ float4 g_Wp[Hsz * Hsz];   // 256 KB, L2-resident
__device__ float4 g_u[Hsz];          // input weights per hidden j, gate order i,f,g,o
__device__ float4 g_b[Hsz];          // b_ih + b_hh per hidden j, gate order i,f,g,o

// ---------------------------------------------------------------------------
// helpers: packed f32x2 FMA (Blackwell), pack/unpack
// ---------------------------------------------------------------------------
__device__ __forceinline__ void ffma2(unsigned long long& acc,
                                      unsigned long long a,
                                      unsigned long long b) {
    asm("fma.rn.f32x2 %0, %1, %2, %0;" : "+l"(acc) : "l"(a), "l"(b));
}

__device__ __forceinline__ unsigned long long pack2(float lo, float hi) {
    unsigned long long v;
    asm("mov.b64 %0, {%1, %2};" : "=l"(v) : "f"(lo), "f"(hi));
    return v;
}

__device__ __forceinline__ float2 unpack2(unsigned long long v) {
    float2 f;
    asm("mov.b64 {%0, %1}, %2;" : "=f"(f.x), "=f"(f.y) : "l"(v));
    return f;
}

// ---------------------------------------------------------------------------
// MUFU-free sigmoid / tanh (FFMA + ALU only).
//   exp(-|x|) = 2^z via round-to-int trick + deg-5 poly + exponent-bit scale
//   1/(1+t) via bit-trick seed + 3 Newton iterations
// abs error < ~2e-7
// ---------------------------------------------------------------------------
__device__ __forceinline__ float fast_sigmoid(float xx) {
    float ax = fminf(fabsf(xx), 20.0f);
    float z  = ax * -1.4426950408889634f;          // -ax * log2(e), in [-28.9, 0]
    float tb = z + 12582912.0f;                    // 1.5 * 2^23 round trick
    float n  = tb - 12582912.0f;                   // round(z)
    float r  = z - n;                              // [-0.5, 0.5]
    int   ni = __float_as_int(tb) - 0x4B400000;    // (int)n
    float p  = 1.3333558e-3f;
    p = fmaf(p, r, 9.6181291e-3f);
    p = fmaf(p, r, 5.5504109e-2f);
    p = fmaf(p, r, 2.4022651e-1f);
    p = fmaf(p, r, 6.9314718e-1f);
    p = fmaf(p, r, 1.0f);                          // 2^r
    float t = __int_as_float(__float_as_int(p) + (ni << 23));  // e^{-ax}
    float d = 1.0f + t;                            // in [1,2]
    float y = __int_as_float(0x7EF311C3 - __float_as_int(d));  // ~1/d seed
    y = y * fmaf(-d, y, 2.0f);
    y = y * fmaf(-d, y, 2.0f);
    y = y * fmaf(-d, y, 2.0f);                     // 1/(1+t)
    return (xx >= 0.0f) ? y : t * y;               // sig(x) or e^{-|x|}/(1+e^{-|x|})
}

__device__ __forceinline__ float fast_tanh(float u) {
    return fmaf(2.0f, fast_sigmoid(2.0f * u), -1.0f);
}

// ---------------------------------------------------------------------------
// prep: repack W_hh into gate-interleaved float4 (k-major), fold biases
// ---------------------------------------------------------------------------
__global__ void lstm_prep_kernel(const float* __restrict__ Whh,
                                 const float* __restrict__ Wih,
                                 const float* __restrict__ bih,
                                 const float* __restrict__ bhh) {
    int idx = blockIdx.x * blockDim.x + threadIdx.x;   // 0 .. 16383
    if (idx >= Hsz * Hsz) return;
    int k = idx >> 7;
    int j = idx & 127;
    float4 w;
    w.x = Whh[(0 * Hsz + j) * Hsz + k];
    w.y = Whh[(1 * Hsz + j) * Hsz + k];
    w.z = Whh[(2 * Hsz + j) * Hsz + k];
    w.w = Whh[(3 * Hsz + j) * Hsz + k];
    g_Wp[idx] = w;
    if (idx < Hsz) {
        float4 u, b;
        u.x = Wih[0 * Hsz + j]; u.y = Wih[1 * Hsz + j];
        u.z = Wih[2 * Hsz + j]; u.w = Wih[3 * Hsz + j];
        b.x = bih[0 * Hsz + j] + bhh[0 * Hsz + j];
        b.y = bih[1 * Hsz + j] + bhh[1 * Hsz + j];
        b.z = bih[2 * Hsz + j] + bhh[2 * Hsz + j];
        b.w = bih[3 * Hsz + j] + bhh[3 * Hsz + j];
        g_u[j] = u;
        g_b[j] = b;
    }
}

// ---------------------------------------------------------------------------
// main persistent kernel: 128 CTAs x 512 threads, 16 batch rows per CTA.
// thread (j = tid&127, rg = tid>>7) owns hidden unit j for rows rg*4..rg*4+3.
// h kept in SMEM as lane-duplicated float2 pairs, double buffered.
// ---------------------------------------------------------------------------
#define HPAD 18   // row-dim padding: keeps 16B alignment (even) + spreads STS banks

__global__ __launch_bounds__(NTHREADS, 1)
void lstm_main_kernel(const float* __restrict__ x,
                      const float* __restrict__ hx0,
                      const float* __restrict__ cx0,
                      const float* __restrict__ Wm,
                      const float* __restrict__ bm,
                      float* __restrict__ out) {
    __shared__ __align__(16) float2 shH[2][Hsz][HPAD];  // [buf][k][row] = {h,h}
    __shared__ float shX[2][ROWS_PER_CTA];

    const int tid = threadIdx.x;
    const int j   = tid & 127;
    const int rg  = tid >> 7;            // 0..3
    const int r0  = rg * 4;              // first local row
    const int rowbase = blockIdx.x * ROWS_PER_CTA;

    const float4 u = g_u[j];
    const float4 b = g_b[j];

    float c[4], h[4];
#pragma unroll
    for (int r = 0; r < 4; r++) {
        int row = rowbase + r0 + r;
        h[r] = hx0[row * Hsz + j];
        c[r] = cx0[row * Hsz + j];
        shH[0][j][r0 + r] = make_float2(h[r], h[r]);
    }
    if (tid < ROWS_PER_CTA) shX[0][tid] = x[(rowbase + tid) * Tsz + 0];
    __syncthreads();

    const ulonglong2* __restrict__ Wp2 = reinterpret_cast<const ulonglong2*>(g_Wp);

    for (int t = 0; t < Tsz; t++) {
        const int cur = t & 1, nxt = cur ^ 1;

        // init gate accumulators: x-contribution + bias (packed {i,f} and {g,o})
        unsigned long long accIF[4], accGO[4];
#pragma unroll
        for (int r = 0; r < 4; r++) {
            float xv = shX[cur][r0 + r];
            accIF[r] = pack2(fmaf(xv, u.x, b.x), fmaf(xv, u.y, b.y));
            accGO[r] = pack2(fmaf(xv, u.z, b.z), fmaf(xv, u.w, b.w));
        }

        // gates += h @ W^T : 128 k-iters of 1 LDG.128 + 2 broadcast LDS.128 + 8 FFMA2
        const char* hrow = reinterpret_cast<const char*>(&shH[cur][0][r0]);
#pragma unroll 4
        for (int k = 0; k < Hsz; k++) {
            ulonglong2 w = Wp2[k * Hsz + j];   // {wi,wf},{wg,wo} for this (k,j)
            ulonglong2 hp01 = *reinterpret_cast<const ulonglong2*>(hrow + (size_t)k * (HPAD * 8));
            ulonglong2 hp23 = *reinterpret_cast<const ulonglong2*>(hrow + (size_t)k * (HPAD * 8) + 16);
            ffma2(accIF[0], w.x, hp01.x); ffma2(accGO[0], w.y, hp01.x);
            ffma2(accIF[1], w.x, hp01.y); ffma2(accGO[1], w.y, hp01.y);
            ffma2(accIF[2], w.x, hp23.x); ffma2(accGO[2], w.y, hp23.x);
            ffma2(accIF[3], w.x, hp23.y); ffma2(accGO[3], w.y, hp23.y);
        }

        // epilogue: gate nonlinearities + state update (MUFU-free)
#pragma unroll
        for (int r = 0; r < 4; r++) {
            float2 aIF = unpack2(accIF[r]);
            float2 aGO = unpack2(accGO[r]);
            float iv = fast_sigmoid(aIF.x);
            float fv = fast_sigmoid(aIF.y);
            float gv = fast_tanh(aGO.x);
            float ov = fast_sigmoid(aGO.y);
            c[r] = fmaf(fv, c[r], iv * gv);
            h[r] = ov * fast_tanh(c[r]);
            shH[nxt][j][r0 + r] = make_float2(h[r], h[r]);
        }

        // prefetch next x
        if (tid < ROWS_PER_CTA && (t + 1) < Tsz)
            shX[nxt][tid] = x[(rowbase + tid) * Tsz + (t + 1)];

        __syncthreads();
    }

    // final head: out[row] = sigmoid(sum_j h[row][j] * Wm[j] + bm)
    float wm = Wm[j];
    float* sf = reinterpret_cast<float*>(&shH[0][0][0]);  // scratch [16][128]
#pragma unroll
    for (int r = 0; r < 4; r++)
        sf[(r0 + r) * Hsz + j] = h[r] * wm;
    __syncthreads();

    if (tid < ROWS_PER_CTA) {
        float s = 0.0f;
        for (int k = 0; k < Hsz; k++) s += sf[tid * Hsz + k];
        s += bm[0];
        out[rowbase + tid] = fast_sigmoid(s);
    }
}

// ---------------------------------------------------------------------------
extern "C" void kernel_launch(void* const* d_in, const int* in_sizes, int n_in,
                              void* d_out, int out_size) {
    const float* x    = (const float*)d_in[0];
    const float* hx0  = (const float*)d_in[1];
    const float* cx0  = (const float*)d_in[2];
    const float* Wih  = (const float*)d_in[3];
    const float* Whh  = (const float*)d_in[4];
    const float* bih  = (const float*)d_in[5];
    const float* bhh  = (const float*)d_in[6];
    const float* Wmlp = (const float*)d_in[7];
    const float* bmlp = (const float*)d_in[8];
    float* out = (float*)d_out;

    lstm_prep_kernel<<<(Hsz * Hsz + 255) / 256, 256>>>(Whh, Wih, bih, bhh);
    lstm_main_kernel<<<NCTA, NTHREADS>>>(x, hx0, cx0, Wmlp, bmlp, out);
}

// round 3
// speedup vs baseline: 1.4192x; 1.4192x over previous
#include <cuda_runtime.h>
#include <cuda_bf16.h>

// LSTM_discriminator: B=2048, T=512, H=128, input dim 1.
// inputs: 0:x[2048,512] 1:hx0[2048,128] 2:cx0[2048,128] 3:W_ih[512,1]
//         4:W_hh[512,128] 5:b_ih[512] 6:b_hh[512] 7:W_mlp[1,128] 8:b_mlp[1]
// output: sigmoid(h_T @ W_mlp^T + b_mlp) -> [2048,1] fp32

#define Bsz 2048
#define Tsz 512
#define Hsz 128
#define ROWS_PER_CTA 16
#define RPT 8                        // rows per thread
#define NCTA (Bsz / ROWS_PER_CTA)   // 128
#define NTHREADS (ROWS_PER_CTA * Hsz / RPT)  // 256
#define ROWSP 20                    // padded row stride (floats): 16B-aligned LDS, conflict-spread STS

typedef unsigned long long ull;

// Packed recurrent weights: g_Wp[k*128 + j] = {W_hh[j][k], W_hh[128+j][k], W_hh[256+j][k], W_hh[384+j][k]}
__device__ float4 g_Wp[Hsz * Hsz];   // 256 KB, L2-resident
__device__ float4 g_u[Hsz];          // input weights per hidden j, gate order i,f,g,o
__device__ float4 g_b[Hsz];          // b_ih + b_hh per hidden j

// ---------------------------------------------------------------------------
// packed f32x2 FMA (Blackwell PTX-only dual-lane FFMA)
// ---------------------------------------------------------------------------
__device__ __forceinline__ void ffma2(ull& acc, ull a, ull b) {
    asm("fma.rn.f32x2 %0, %1, %2, %0;" : "+l"(acc) : "l"(a), "l"(b));
}
__device__ __forceinline__ ull pack2(float lo, float hi) {
    ull v; asm("mov.b64 %0, {%1, %2};" : "=l"(v) : "f"(lo), "f"(hi)); return v;
}
__device__ __forceinline__ float2 unpack2(ull v) {
    float2 f; asm("mov.b64 {%0, %1}, %2;" : "=f"(f.x), "=f"(f.y) : "l"(v)); return f;
}

// ---------------------------------------------------------------------------
// MUFU-based nonlinearities (ex2 + rcp): 4-5 instr each, ~1e-7 abs err
// ---------------------------------------------------------------------------
__device__ __forceinline__ float ex2a(float x) {
    float r; asm("ex2.approx.f32 %0, %1;" : "=f"(r) : "f"(x)); return r;
}
__device__ __forceinline__ float rcpa(float x) {
    float r; asm("rcp.approx.f32 %0, %1;" : "=f"(r) : "f"(x)); return r;
}
__device__ __forceinline__ float fsig(float x) {
    // sigmoid(x) = 1 / (1 + 2^(-x*log2 e))
    return rcpa(1.0f + ex2a(x * -1.4426950408889634f));
}
__device__ __forceinline__ float ftanh(float x) {
    // tanh(x) = 2*sigmoid(2x) - 1
    return fmaf(2.0f, rcpa(1.0f + ex2a(x * -2.8853900817779268f)), -1.0f);
}

// ---------------------------------------------------------------------------
// prep: repack W_hh gate-interleaved (k-major), fold biases
// ---------------------------------------------------------------------------
__global__ void lstm_prep_kernel(const float* __restrict__ Whh,
                                 const float* __restrict__ Wih,
                                 const float* __restrict__ bih,
                                 const float* __restrict__ bhh) {
    int idx = blockIdx.x * blockDim.x + threadIdx.x;
    if (idx >= Hsz * Hsz) return;
    int k = idx >> 7;
    int j = idx & 127;
    float4 w;
    w.x = Whh[(0 * Hsz + j) * Hsz + k];
    w.y = Whh[(1 * Hsz + j) * Hsz + k];
    w.z = Whh[(2 * Hsz + j) * Hsz + k];
    w.w = Whh[(3 * Hsz + j) * Hsz + k];
    g_Wp[idx] = w;
    if (idx < Hsz) {
        float4 u, b;
        u.x = Wih[0 * Hsz + j]; u.y = Wih[1 * Hsz + j];
        u.z = Wih[2 * Hsz + j]; u.w = Wih[3 * Hsz + j];
        b.x = bih[0 * Hsz + j] + bhh[0 * Hsz + j];
        b.y = bih[1 * Hsz + j] + bhh[1 * Hsz + j];
        b.z = bih[2 * Hsz + j] + bhh[2 * Hsz + j];
        b.w = bih[3 * Hsz + j] + bhh[3 * Hsz + j];
        g_u[j] = u;
        g_b[j] = b;
    }
}

// ---------------------------------------------------------------------------
// main persistent kernel: 128 CTAs x 256 threads, 16 batch rows per CTA,
// 8 rows per thread. thread (j = tid&127, rg = tid>>7) owns hidden unit j
// for rows rg*8 .. rg*8+7. h in SMEM un-duplicated, double buffered.
// ---------------------------------------------------------------------------
__global__ __launch_bounds__(NTHREADS, 1)
void lstm_main_kernel(const float* __restrict__ x,
                      const float* __restrict__ hx0,
                      const float* __restrict__ cx0,
                      const float* __restrict__ Wm,
                      const float* __restrict__ bm,
                      float* __restrict__ out) {
    __shared__ __align__(16) float shH[2][Hsz][ROWSP];   // [buf][k][row]
    __shared__ float shX[2][ROWS_PER_CTA];

    const int tid = threadIdx.x;
    const int j   = tid & 127;
    const int rg  = tid >> 7;            // 0..1
    const int r0  = rg * RPT;            // 0 or 8
    const int rowbase = blockIdx.x * ROWS_PER_CTA;

    const float4 u = g_u[j];
    const float4 b = g_b[j];

    float c[RPT], h[RPT];
#pragma unroll
    for (int r = 0; r < RPT; r++) {
        int row = rowbase + r0 + r;
        h[r] = hx0[row * Hsz + j];
        c[r] = cx0[row * Hsz + j];
        shH[0][j][r0 + r] = h[r];
    }
    if (tid < ROWS_PER_CTA) shX[0][tid] = x[(rowbase + tid) * Tsz + 0];
    __syncthreads();

    const float4* __restrict__ Wp = g_Wp + j;

    for (int t = 0; t < Tsz; t++) {
        const int cur = t & 1, nxt = cur ^ 1;

        // init gate accumulators: x-contribution + bias; row-pairs packed f32x2
        ull aI[4], aF[4], aG[4], aO[4];
#pragma unroll
        for (int p = 0; p < 4; p++) {
            float x0 = shX[cur][r0 + 2 * p];
            float x1 = shX[cur][r0 + 2 * p + 1];
            aI[p] = pack2(fmaf(x0, u.x, b.x), fmaf(x1, u.x, b.x));
            aF[p] = pack2(fmaf(x0, u.y, b.y), fmaf(x1, u.y, b.y));
            aG[p] = pack2(fmaf(x0, u.z, b.z), fmaf(x1, u.z, b.z));
            aO[p] = pack2(fmaf(x0, u.w, b.w), fmaf(x1, u.w, b.w));
        }

        // gates += h @ W^T : per k: 1 LDG.128(W) + 2 bcast LDS.128(h) + 4 mov + 16 FFMA2
        const char* hbase = reinterpret_cast<const char*>(&shH[cur][0][r0]);
#pragma unroll 8
        for (int k = 0; k < Hsz; k++) {
            float4 w = Wp[k * Hsz];
            ull wI = pack2(w.x, w.x);
            ull wF = pack2(w.y, w.y);
            ull wG = pack2(w.z, w.z);
            ull wO = pack2(w.w, w.w);
            ulonglong2 ha = *reinterpret_cast<const ulonglong2*>(hbase + (size_t)k * (ROWSP * 4));
            ulonglong2 hb = *reinterpret_cast<const ulonglong2*>(hbase + (size_t)k * (ROWSP * 4) + 16);
            ffma2(aI[0], wI, ha.x); ffma2(aI[1], wI, ha.y);
            ffma2(aI[2], wI, hb.x); ffma2(aI[3], wI, hb.y);
            ffma2(aF[0], wF, ha.x); ffma2(aF[1], wF, ha.y);
            ffma2(aF[2], wF, hb.x); ffma2(aF[3], wF, hb.y);
            ffma2(aG[0], wG, ha.x); ffma2(aG[1], wG, ha.y);
            ffma2(aG[2], wG, hb.x); ffma2(aG[3], wG, hb.y);
            ffma2(aO[0], wO, ha.x); ffma2(aO[1], wO, ha.y);
            ffma2(aO[2], wO, hb.x); ffma2(aO[3], wO, hb.y);
        }

        // epilogue: MUFU gates + state update; write h pairs back (8B stores)
#pragma unroll
        for (int p = 0; p < 4; p++) {
            float2 iv = unpack2(aI[p]);
            float2 fv = unpack2(aF[p]);
            float2 gv = unpack2(aG[p]);
            float2 ov = unpack2(aO[p]);
            int ra = 2 * p, rb = 2 * p + 1;
            c[ra] = fmaf(fsig(fv.x), c[ra], fsig(iv.x) * ftanh(gv.x));
            c[rb] = fmaf(fsig(fv.y), c[rb], fsig(iv.y) * ftanh(gv.y));
            h[ra] = fsig(ov.x) * ftanh(c[ra]);
            h[rb] = fsig(ov.y) * ftanh(c[rb]);
            *reinterpret_cast<float2*>(&shH[nxt][j][r0 + ra]) = make_float2(h[ra], h[rb]);
        }

        // prefetch next x
        if (tid < ROWS_PER_CTA && (t + 1) < Tsz)
            shX[nxt][tid] = x[(rowbase + tid) * Tsz + (t + 1)];

        __syncthreads();
    }

    // final head: out[row] = sigmoid(sum_j h[row][j] * Wm[j] + bm)
    float wm = Wm[j];
    float* sf = reinterpret_cast<float*>(&shH[0][0][0]);  // scratch [16][128]
    __syncthreads();
#pragma unroll
    for (int r = 0; r < RPT; r++)
        sf[(r0 + r) * Hsz + j] = h[r] * wm;
    __syncthreads();

    if (tid < ROWS_PER_CTA) {
        float s = 0.0f;
#pragma unroll 8
        for (int k = 0; k < Hsz; k++) s += sf[tid * Hsz + k];
        s += bm[0];
        out[rowbase + tid] = fsig(s);
    }
}

// ---------------------------------------------------------------------------
extern "C" void kernel_launch(void* const* d_in, const int* in_sizes, int n_in,
                              void* d_out, int out_size) {
    const float* x    = (const float*)d_in[0];
    const float* hx0  = (const float*)d_in[1];
    const float* cx0  = (const float*)d_in[2];
    const float* Wih  = (const float*)d_in[3];
    const float* Whh  = (const float*)d_in[4];
    const float* bih  = (const float*)d_in[5];
    const float* bhh  = (const float*)d_in[6];
    const float* Wmlp = (const float*)d_in[7];
    const float* bmlp = (const float*)d_in[8];
    float* out = (float*)d_out;

    lstm_prep_kernel<<<(Hsz * Hsz + 255) / 256, 256>>>(Whh, Wih, bih, bhh);
    lstm_main_kernel<<<NCTA, NTHREADS>>>(x, hx0, cx0, Wmlp, bmlp, out);
}

// round 4
// speedup vs baseline: 1.7190x; 1.2113x over previous
#include <cuda_runtime.h>
#include <cuda_bf16.h>

// LSTM_discriminator: B=2048, T=512, H=128, input dim 1.
// inputs: 0:x[2048,512] 1:hx0[2048,128] 2:cx0[2048,128] 3:W_ih[512,1]
//         4:W_hh[512,128] 5:b_ih[512] 6:b_hh[512] 7:W_mlp[1,128] 8:b_mlp[1]
// output: sigmoid(h_T @ W_mlp^T + b_mlp) -> [2048,1] fp32

#define Bsz 2048
#define Tsz 512
#define Hsz 128
#define ROWS_PER_CTA 16
#define RPT 8                        // rows per thread
#define NCTA (Bsz / ROWS_PER_CTA)   // 128
#define NTHREADS (ROWS_PER_CTA * Hsz / RPT)  // 256
#define ROWSP 20                    // padded row stride (floats)
#define KSM 96                      // k-rows of W resident in SMEM (96*128*16B = 192KB)

typedef unsigned long long ull;

// Packed recurrent weights: g_Wp[k*128 + j] = {W_hh[j][k], W_hh[128+j][k], W_hh[256+j][k], W_hh[384+j][k]}
__device__ float4 g_Wp[Hsz * Hsz];   // 256 KB
__device__ float4 g_u[Hsz];          // input weights per hidden j, gate order i,f,g,o
__device__ float4 g_b[Hsz];          // b_ih + b_hh per hidden j

// ---------------------------------------------------------------------------
// packed f32x2 FMA (Blackwell PTX-only dual-lane FFMA)
// ---------------------------------------------------------------------------
__device__ __forceinline__ void ffma2(ull& acc, ull a, ull b) {
    asm("fma.rn.f32x2 %0, %1, %2, %0;" : "+l"(acc) : "l"(a), "l"(b));
}
__device__ __forceinline__ ull pack2(float lo, float hi) {
    ull v; asm("mov.b64 %0, {%1, %2};" : "=l"(v) : "f"(lo), "f"(hi)); return v;
}
__device__ __forceinline__ float2 unpack2(ull v) {
    float2 f; asm("mov.b64 {%0, %1}, %2;" : "=f"(f.x), "=f"(f.y) : "l"(v)); return f;
}

// ---------------------------------------------------------------------------
// MUFU-based nonlinearities (ex2 + rcp)
// ---------------------------------------------------------------------------
__device__ __forceinline__ float ex2a(float x) {
    float r; asm("ex2.approx.f32 %0, %1;" : "=f"(r) : "f"(x)); return r;
}
__device__ __forceinline__ float rcpa(float x) {
    float r; asm("rcp.approx.f32 %0, %1;" : "=f"(r) : "f"(x)); return r;
}
__device__ __forceinline__ float fsig(float x) {
    return rcpa(1.0f + ex2a(x * -1.4426950408889634f));
}
__device__ __forceinline__ float ftanh(float x) {
    return fmaf(2.0f, rcpa(1.0f + ex2a(x * -2.8853900817779268f)), -1.0f);
}

// ---------------------------------------------------------------------------
// prep: repack W_hh gate-interleaved (k-major), fold biases
// ---------------------------------------------------------------------------
__global__ void lstm_prep_kernel(const float* __restrict__ Whh,
                                 const float* __restrict__ Wih,
                                 const float* __restrict__ bih,
                                 const float* __restrict__ bhh) {
    int idx = blockIdx.x * blockDim.x + threadIdx.x;
    if (idx >= Hsz * Hsz) return;
    int k = idx >> 7;
    int j = idx & 127;
    float4 w;
    w.x = Whh[(0 * Hsz + j) * Hsz + k];
    w.y = Whh[(1 * Hsz + j) * Hsz + k];
    w.z = Whh[(2 * Hsz + j) * Hsz + k];
    w.w = Whh[(3 * Hsz + j) * Hsz + k];
    g_Wp[idx] = w;
    if (idx < Hsz) {
        float4 u, b;
        u.x = Wih[0 * Hsz + j]; u.y = Wih[1 * Hsz + j];
        u.z = Wih[2 * Hsz + j]; u.w = Wih[3 * Hsz + j];
        b.x = bih[0 * Hsz + j] + bhh[0 * Hsz + j];
        b.y = bih[1 * Hsz + j] + bhh[1 * Hsz + j];
        b.z = bih[2 * Hsz + j] + bhh[2 * Hsz + j];
        b.w = bih[3 * Hsz + j] + bhh[3 * Hsz + j];
        g_u[j] = u;
        g_b[j] = b;
    }
}

// ---------------------------------------------------------------------------
// main persistent kernel: 128 CTAs x 256 threads, 16 batch rows per CTA,
// 8 rows per thread. thread (j = tid&127, rg = tid>>7) owns hidden unit j
// for rows rg*8 .. rg*8+7. h in SMEM, double buffered. W k<KSM in SMEM.
// ---------------------------------------------------------------------------

// dynamic smem layout (bytes):
//   [0, KSM*128*16)                      : sW   float4[KSM][128]   192 KB
//   [WOFF, WOFF + 2*128*ROWSP*4)         : shH  float[2][128][ROWSP]
//   [XOFF, XOFF + 2*16*4)                : shX  float[2][16]
#define WBYTES (KSM * Hsz * 16)
#define HBYTES (2 * Hsz * ROWSP * 4)
#define DSMEM  (WBYTES + HBYTES + 2 * ROWS_PER_CTA * 4)

__global__ __launch_bounds__(NTHREADS, 1)
void lstm_main_kernel(const float* __restrict__ x,
                      const float* __restrict__ hx0,
                      const float* __restrict__ cx0,
                      const float* __restrict__ Wm,
                      const float* __restrict__ bm,
                      float* __restrict__ out) {
    extern __shared__ __align__(16) char dyn[];
    float4* sW = reinterpret_cast<float4*>(dyn);
    float (*shH)[Hsz][ROWSP] = reinterpret_cast<float (*)[Hsz][ROWSP]>(dyn + WBYTES);
    float (*shX)[ROWS_PER_CTA] = reinterpret_cast<float (*)[ROWS_PER_CTA]>(dyn + WBYTES + HBYTES);

    const int tid = threadIdx.x;
    const int j   = tid & 127;
    const int rg  = tid >> 7;            // 0..1
    const int r0  = rg * RPT;            // 0 or 8
    const int rowbase = blockIdx.x * ROWS_PER_CTA;

    // fill SMEM-resident W slice (once; amortized over 512 steps)
    for (int i = tid; i < KSM * Hsz; i += NTHREADS)
        sW[i] = g_Wp[i];

    const float4 u = g_u[j];
    const float4 b = g_b[j];

    float c[RPT], h[RPT];
#pragma unroll
    for (int r = 0; r < RPT; r++) {
        int row = rowbase + r0 + r;
        h[r] = hx0[row * Hsz + j];
        c[r] = cx0[row * Hsz + j];
        shH[0][j][r0 + r] = h[r];
    }
    if (tid < ROWS_PER_CTA) shX[0][tid] = x[(rowbase + tid) * Tsz + 0];
    __syncthreads();

    const float4* __restrict__ Wg = g_Wp + j;   // global part, k >= KSM
    const float4* __restrict__ Ws = sW + j;     // smem part,   k <  KSM

    for (int t = 0; t < Tsz; t++) {
        const int cur = t & 1, nxt = cur ^ 1;

        // init gate accumulators: x-contribution + bias; row-pairs packed f32x2
        ull aI[4], aF[4], aG[4], aO[4];
#pragma unroll
        for (int p = 0; p < 4; p++) {
            float x0 = shX[cur][r0 + 2 * p];
            float x1 = shX[cur][r0 + 2 * p + 1];
            aI[p] = pack2(fmaf(x0, u.x, b.x), fmaf(x1, u.x, b.x));
            aF[p] = pack2(fmaf(x0, u.y, b.y), fmaf(x1, u.y, b.y));
            aG[p] = pack2(fmaf(x0, u.z, b.z), fmaf(x1, u.z, b.z));
            aO[p] = pack2(fmaf(x0, u.w, b.w), fmaf(x1, u.w, b.w));
        }

        const char* hbase = reinterpret_cast<const char*>(&shH[cur][0][r0]);

#define KBODY(WSRC, kk)                                                         \
        {                                                                       \
            float4 w = WSRC;                                                    \
            ull wI = pack2(w.x, w.x);                                           \
            ull wF = pack2(w.y, w.y);                                           \
            ull wG = pack2(w.z, w.z);                                           \
            ull wO = pack2(w.w, w.w);                                           \
            ulonglong2 ha = *reinterpret_cast<const ulonglong2*>(hbase + (size_t)(kk) * (ROWSP * 4));      \
            ulonglong2 hb = *reinterpret_cast<const ulonglong2*>(hbase + (size_t)(kk) * (ROWSP * 4) + 16); \
            ffma2(aI[0], wI, ha.x); ffma2(aI[1], wI, ha.y);                     \
            ffma2(aI[2], wI, hb.x); ffma2(aI[3], wI, hb.y);                     \
            ffma2(aF[0], wF, ha.x); ffma2(aF[1], wF, ha.y);                     \
            ffma2(aF[2], wF, hb.x); ffma2(aF[3], wF, hb.y);                     \
            ffma2(aG[0], wG, ha.x); ffma2(aG[1], wG, ha.y);                     \
            ffma2(aG[2], wG, hb.x); ffma2(aG[3], wG, hb.y);                     \
            ffma2(aO[0], wO, ha.x); ffma2(aO[1], wO, ha.y);                     \
            ffma2(aO[2], wO, hb.x); ffma2(aO[3], wO, hb.y);                     \
        }

        // k < KSM : W from SMEM (LDS, 29cyc)
#pragma unroll 8
        for (int k = 0; k < KSM; k++)
            KBODY(Ws[k * Hsz], k)

        // k >= KSM : W from global (64KB working set -> L1-resident)
#pragma unroll 8
        for (int k = KSM; k < Hsz; k++)
            KBODY(Wg[k * Hsz], k)
#undef KBODY

        // epilogue: MUFU gates + state update; write h pairs back (8B stores)
#pragma unroll
        for (int p = 0; p < 4; p++) {
            float2 iv = unpack2(aI[p]);
            float2 fv = unpack2(aF[p]);
            float2 gv = unpack2(aG[p]);
            float2 ov = unpack2(aO[p]);
            int ra = 2 * p, rb = 2 * p + 1;
            c[ra] = fmaf(fsig(fv.x), c[ra], fsig(iv.x) * ftanh(gv.x));
            c[rb] = fmaf(fsig(fv.y), c[rb], fsig(iv.y) * ftanh(gv.y));
            h[ra] = fsig(ov.x) * ftanh(c[ra]);
            h[rb] = fsig(ov.y) * ftanh(c[rb]);
            *reinterpret_cast<float2*>(&shH[nxt][j][r0 + ra]) = make_float2(h[ra], h[rb]);
        }

        // prefetch next x
        if (tid < ROWS_PER_CTA && (t + 1) < Tsz)
            shX[nxt][tid] = x[(rowbase + tid) * Tsz + (t + 1)];

        __syncthreads();
    }

    // final head: out[row] = sigmoid(sum_j h[row][j] * Wm[j] + bm)
    float wm = Wm[j];
    float* sf = reinterpret_cast<float*>(&shH[0][0][0]);  // scratch [16][128]
    __syncthreads();
#pragma unroll
    for (int r = 0; r < RPT; r++)
        sf[(r0 + r) * Hsz + j] = h[r] * wm;
    __syncthreads();

    if (tid < ROWS_PER_CTA) {
        float s = 0.0f;
#pragma unroll 8
        for (int k = 0; k < Hsz; k++) s += sf[tid * Hsz + k];
        s += bm[0];
        out[rowbase + tid] = fsig(s);
    }
}

// ---------------------------------------------------------------------------
extern "C" void kernel_launch(void* const* d_in, const int* in_sizes, int n_in,
                              void* d_out, int out_size) {
    const float* x    = (const float*)d_in[0];
    const float* hx0  = (const float*)d_in[1];
    const float* cx0  = (const float*)d_in[2];
    const float* Wih  = (const float*)d_in[3];
    const float* Whh  = (const float*)d_in[4];
    const float* bih  = (const float*)d_in[5];
    const float* bhh  = (const float*)d_in[6];
    const float* Wmlp = (const float*)d_in[7];
    const float* bmlp = (const float*)d_in[8];
    float* out = (float*)d_out;

    cudaFuncSetAttribute(lstm_main_kernel,
                         cudaFuncAttributeMaxDynamicSharedMemorySize, DSMEM);

    lstm_prep_kernel<<<(Hsz * Hsz + 255) / 256, 256>>>(Whh, Wih, bih, bhh);
    lstm_main_kernel<<<NCTA, NTHREADS, DSMEM>>>(x, hx0, cx0, Wmlp, bmlp, out);
}

// round 6
// speedup vs baseline: 5.4776x; 3.1865x over previous
#include <cuda_runtime.h>
#include <cuda_fp16.h>
#include <cstdint>

// LSTM_discriminator: B=2048, T=512, H=128, input dim 1.
// inputs: 0:x[2048,512] 1:hx0[2048,128] 2:cx0[2048,128] 3:W_ih[512,1]
//         4:W_hh[512,128] 5:b_ih[512] 6:b_hh[512] 7:W_mlp[1,128] 8:b_mlp[1]
// output: sigmoid(h_T @ W_mlp^T + b_mlp) -> [2048,1] fp32
//
// Tensor path (base-target PTX, works under compute_103):
//   gates[512,16] = W_fp16[512,128] @ (h_hi + h_lo)[128,16]  per step,
//   via mma.sync.m16n8k16 f16->f32, W fragments register-resident.

#define Bsz 2048
#define Tsz 512
#define Hsz 128
#define ROWS_PER_CTA 16
#define NCTA (Bsz / ROWS_PER_CTA)    // 128
#define NTHREADS 512
#define NPAD 20                      // gates row stride in floats (80B: 16B-aligned, bank-spread)
#define HSTRIDE 48                   // h row stride in bytes (32B data + 16B pad: LDSM conflict-free)

// dynamic SMEM layout (bytes); A-staging (128KB) aliases the whole region at startup
#define OFF_G   0                              // gates f32 [512][NPAD] = 40960
#define OFF_HHI 40960                          // h_hi  f16 [128][HSTRIDE] = 6144
#define OFF_HLO (OFF_HHI + 6144)               // h_lo
#define OFF_X   (OFF_HLO + 6144)               // float [2][16]
#define STAGE_BYTES (512 * 128 * 2)            // 131072
#define DSMEM STAGE_BYTES

typedef unsigned int uint;

__device__ __align__(16) __half g_Whh16[512 * 128];  // fp16 W_hh, original row-major
__device__ float4 g_u[Hsz];   // W_ih per hidden j, gate order i,f,g,o
__device__ float4 g_b[Hsz];   // b_ih + b_hh per hidden j

// ---------------------------------------------------------------------------
__device__ __forceinline__ uint32_t smem_u32(const void* p) {
    uint32_t a;
    asm("{ .reg .u64 t; cvta.to.shared.u64 t, %1; cvt.u32.u64 %0, t; }" : "=r"(a) : "l"(p));
    return a;
}
__device__ __forceinline__ void ldsm_x4(uint32_t* r, uint32_t addr) {
    asm volatile("ldmatrix.sync.aligned.m8n8.x4.shared.b16 {%0,%1,%2,%3}, [%4];"
        : "=r"(r[0]), "=r"(r[1]), "=r"(r[2]), "=r"(r[3]) : "r"(addr));
}
__device__ __forceinline__ void ldsm_x4_t(uint32_t* r, uint32_t addr) {
    asm volatile("ldmatrix.sync.aligned.m8n8.x4.trans.shared.b16 {%0,%1,%2,%3}, [%4];"
        : "=r"(r[0]), "=r"(r[1]), "=r"(r[2]), "=r"(r[3]) : "r"(addr));
}
__device__ __forceinline__ void mma16816(float* d, const uint32_t* a, uint32_t b0, uint32_t b1) {
    asm volatile(
        "mma.sync.aligned.m16n8k16.row.col.f32.f16.f16.f32 "
        "{%0,%1,%2,%3}, {%4,%5,%6,%7}, {%8,%9}, {%0,%1,%2,%3};"
        : "+f"(d[0]), "+f"(d[1]), "+f"(d[2]), "+f"(d[3])
        : "r"(a[0]), "r"(a[1]), "r"(a[2]), "r"(a[3]), "r"(b0), "r"(b1));
}
// MUFU nonlinearities
__device__ __forceinline__ float ex2a(float x) { float r; asm("ex2.approx.f32 %0, %1;" : "=f"(r) : "f"(x)); return r; }
__device__ __forceinline__ float rcpa(float x) { float r; asm("rcp.approx.f32 %0, %1;" : "=f"(r) : "f"(x)); return r; }
__device__ __forceinline__ float fsig(float x)  { return rcpa(1.0f + ex2a(x * -1.4426950408889634f)); }
__device__ __forceinline__ float ftanh(float x) { return fmaf(2.0f, rcpa(1.0f + ex2a(x * -2.8853900817779268f)), -1.0f); }

// ---------------------------------------------------------------------------
// prep: W_hh -> fp16 (row-major, unchanged layout); pack u, fold biases
// ---------------------------------------------------------------------------
__global__ void lstm_prep_kernel(const float* __restrict__ Whh,
                                 const float* __restrict__ Wih,
                                 const float* __restrict__ bih,
                                 const float* __restrict__ bhh) {
    int idx = blockIdx.x * blockDim.x + threadIdx.x;
    if (idx >= 512 * 128) return;
    g_Whh16[idx] = __float2half_rn(Whh[idx]);
    if (idx < Hsz) {
        int j = idx;
        float4 u, b;
        u.x = Wih[0 * Hsz + j]; u.y = Wih[1 * Hsz + j];
        u.z = Wih[2 * Hsz + j]; u.w = Wih[3 * Hsz + j];
        b.x = bih[0 * Hsz + j] + bhh[0 * Hsz + j];
        b.y = bih[1 * Hsz + j] + bhh[1 * Hsz + j];
        b.z = bih[2 * Hsz + j] + bhh[2 * Hsz + j];
        b.w = bih[3 * Hsz + j] + bhh[3 * Hsz + j];
        g_u[j] = u;
        g_b[j] = b;
    }
}

// ---------------------------------------------------------------------------
// main persistent kernel: 128 CTAs x 512 threads (16 warps).
// MMA: warp w owns gate-rows [w*32, w*32+32) (2 m-tiles), all K, N=16.
// Epilogue: thread (j = tid&127, q = tid>>7) owns hidden j, batch cols q*4..+3.
// ---------------------------------------------------------------------------
__global__ __launch_bounds__(NTHREADS, 1)
void lstm_main_kernel(const float* __restrict__ x,
                      const float* __restrict__ hx0,
                      const float* __restrict__ cx0,
                      const float* __restrict__ Wm,
                      const float* __restrict__ bm,
                      float* __restrict__ out) {
    extern __shared__ __align__(16) char dyn[];
    const uint32_t smem_base = smem_u32(dyn);

    const int tid  = threadIdx.x;
    const int w    = tid >> 5;
    const int lane = tid & 31;
    const int j    = tid & 127;
    const int q    = tid >> 7;          // 0..3: batch col group
    const int rowbase = blockIdx.x * ROWS_PER_CTA;

    float* gp  = reinterpret_cast<float*>(dyn + OFF_G);
    float* shX = reinterpret_cast<float*>(dyn + OFF_X);   // [2][16]

    // ---- stage W fp16 into SMEM, then ldmatrix A fragments into registers ----
    {
        const uint4* src = reinterpret_cast<const uint4*>(g_Whh16);
        uint4* dst = reinterpret_cast<uint4*>(dyn);
        for (int i = tid; i < 512 * 128 * 2 / 16; i += NTHREADS) dst[i] = src[i];
    }
    __syncthreads();

    uint32_t Ar[2][8][4];
#pragma unroll
    for (int mt = 0; mt < 2; mt++) {
#pragma unroll
        for (int kt = 0; kt < 8; kt++) {
            int row = w * 32 + mt * 16 + (lane & 15);
            uint32_t byte = (uint32_t)(row * 256 + kt * 32 + (lane >> 4) * 16);
            ldsm_x4(Ar[mt][kt], smem_base + byte);
        }
    }
    __syncthreads();   // A-staging region now free for gates/h/x

    const float4 u = g_u[j];
    const float4 b = g_b[j];

    // ---- init c and h (hi/lo split) ----
    float c[4];
    {
        __half hh[4], hl[4];
#pragma unroll
        for (int bq = 0; bq < 4; bq++) {
            int row_g = rowbase + q * 4 + bq;
            float h = hx0[row_g * Hsz + j];
            c[bq] = cx0[row_g * Hsz + j];
            hh[bq] = __float2half_rn(h);
            hl[bq] = __float2half_rn(h - __half2float(hh[bq]));
        }
        *reinterpret_cast<uint2*>(dyn + OFF_HHI + j * HSTRIDE + q * 8) = *reinterpret_cast<uint2*>(hh);
        *reinterpret_cast<uint2*>(dyn + OFF_HLO + j * HSTRIDE + q * 8) = *reinterpret_cast<uint2*>(hl);
    }
    if (tid < ROWS_PER_CTA) shX[0 * 16 + tid] = x[(rowbase + tid) * Tsz + 0];
    __syncthreads();

    // B-tile ldmatrix lane addressing (fixed per thread)
    const int sub = lane >> 3, r8 = lane & 7;
    const int brow_off = r8 + (sub & 1) * 8;        // + kt*16
    const int bcol_byte = (sub >> 1) * 16;          // n-col 0 or 8, in bytes
    const uint32_t bhi_base = smem_base + OFF_HHI + brow_off * HSTRIDE + bcol_byte;
    const uint32_t blo_base = smem_base + OFF_HLO + brow_off * HSTRIDE + bcol_byte;

    for (int t = 0; t < Tsz; t++) {
        const int cur = t & 1, nxt = cur ^ 1;

        // ---- GEMM: gates = W @ (h_hi + h_lo) ----
        float acc[2][2][4];
#pragma unroll
        for (int mt = 0; mt < 2; mt++)
#pragma unroll
            for (int nt = 0; nt < 2; nt++)
#pragma unroll
                for (int e = 0; e < 4; e++) acc[mt][nt][e] = 0.0f;

#pragma unroll
        for (int kt = 0; kt < 8; kt++) {
            uint32_t bh[4], bl[4];
            ldsm_x4_t(bh, bhi_base + kt * 16 * HSTRIDE);
            ldsm_x4_t(bl, blo_base + kt * 16 * HSTRIDE);
#pragma unroll
            for (int mt = 0; mt < 2; mt++) {
                mma16816(acc[mt][0], Ar[mt][kt], bh[0], bh[1]);
                mma16816(acc[mt][1], Ar[mt][kt], bh[2], bh[3]);
                mma16816(acc[mt][0], Ar[mt][kt], bl[0], bl[1]);
                mma16816(acc[mt][1], Ar[mt][kt], bl[2], bl[3]);
            }
        }

        // ---- scatter gates to SMEM [512][NPAD] f32 ----
#pragma unroll
        for (int mt = 0; mt < 2; mt++) {
#pragma unroll
            for (int nt = 0; nt < 2; nt++) {
                int row = w * 32 + mt * 16 + (lane >> 2);
                int col = nt * 8 + (lane & 3) * 2;
                *reinterpret_cast<float2*>(&gp[row * NPAD + col])       = make_float2(acc[mt][nt][0], acc[mt][nt][1]);
                *reinterpret_cast<float2*>(&gp[(row + 8) * NPAD + col]) = make_float2(acc[mt][nt][2], acc[mt][nt][3]);
            }
        }
        __syncthreads();

        // ---- epilogue: 4 LSTM cells per thread ----
        {
            float4 G[4];
#pragma unroll
            for (int g = 0; g < 4; g++)
                G[g] = *reinterpret_cast<const float4*>(&gp[(g * 128 + j) * NPAD + q * 4]);
            const float* gi = reinterpret_cast<const float*>(&G[0]);
            const float* gf = reinterpret_cast<const float*>(&G[1]);
            const float* gg = reinterpret_cast<const float*>(&G[2]);
            const float* go = reinterpret_cast<const float*>(&G[3]);

            __half hh[4], hl[4];
#pragma unroll
            for (int bq = 0; bq < 4; bq++) {
                float xv = shX[cur * 16 + q * 4 + bq];
                float vi = fsig (gi[bq] + fmaf(xv, u.x, b.x));
                float vf = fsig (gf[bq] + fmaf(xv, u.y, b.y));
                float vg = ftanh(gg[bq] + fmaf(xv, u.z, b.z));
                float vo = fsig (go[bq] + fmaf(xv, u.w, b.w));
                c[bq] = fmaf(vf, c[bq], vi * vg);
                float h = vo * ftanh(c[bq]);
                hh[bq] = __float2half_rn(h);
                hl[bq] = __float2half_rn(h - __half2float(hh[bq]));
            }
            *reinterpret_cast<uint2*>(dyn + OFF_HHI + j * HSTRIDE + q * 8) = *reinterpret_cast<uint2*>(hh);
            *reinterpret_cast<uint2*>(dyn + OFF_HLO + j * HSTRIDE + q * 8) = *reinterpret_cast<uint2*>(hl);
        }

        if (tid < ROWS_PER_CTA && (t + 1) < Tsz)
            shX[nxt * 16 + tid] = x[(rowbase + tid) * Tsz + (t + 1)];

        __syncthreads();
    }

    // ---- recover final h (hi+lo) and apply MLP head ----
    float hfin[4];
    {
        uint2 vh = *reinterpret_cast<uint2*>(dyn + OFF_HHI + j * HSTRIDE + q * 8);
        uint2 vl = *reinterpret_cast<uint2*>(dyn + OFF_HLO + j * HSTRIDE + q * 8);
        const __half* ph = reinterpret_cast<const __half*>(&vh);
        const __half* pl = reinterpret_cast<const __half*>(&vl);
#pragma unroll
        for (int bq = 0; bq < 4; bq++)
            hfin[bq] = __half2float(ph[bq]) + __half2float(pl[bq]);
    }

    float wm = Wm[j];
    float* sf = gp;   // scratch [16][128], reuse gates region
    __syncthreads();
#pragma unroll
    for (int bq = 0; bq < 4; bq++)
        sf[(q * 4 + bq) * Hsz + j] = hfin[bq] * wm;
    __syncthreads();

    if (tid < ROWS_PER_CTA) {
        float s = 0.0f;
#pragma unroll 8
        for (int k = 0; k < Hsz; k++) s += sf[tid * Hsz + k];
        s += bm[0];
        out[rowbase + tid] = fsig(s);
    }
}

// ---------------------------------------------------------------------------
extern "C" void kernel_launch(void* const* d_in, const int* in_sizes, int n_in,
                              void* d_out, int out_size) {
    const float* x    = (const float*)d_in[0];
    const float* hx0  = (const float*)d_in[1];
    const float* cx0  = (const float*)d_in[2];
    const float* Wih  = (const float*)d_in[3];
    const float* Whh  = (const float*)d_in[4];
    const float* bih  = (const float*)d_in[5];
    const float* bhh  = (const float*)d_in[6];
    const float* Wmlp = (const float*)d_in[7];
    const float* bmlp = (const float*)d_in[8];
    float* out = (float*)d_out;

    cudaFuncSetAttribute(lstm_main_kernel,
                         cudaFuncAttributeMaxDynamicSharedMemorySize, DSMEM);

    lstm_prep_kernel<<<(512 * 128 + 255) / 256, 256>>>(Whh, Wih, bih, bhh);
    lstm_main_kernel<<<NCTA, NTHREADS, DSMEM>>>(x, hx0, cx0, Wmlp, bmlp, out);
}

// round 8
// speedup vs baseline: 7.5859x; 1.3849x over previous
#include <cuda_runtime.h>
#include <cuda_fp16.h>
#include <cstdint>

// LSTM_discriminator: B=2048, T=512, H=128, input dim 1.
// inputs: 0:x[2048,512] 1:hx0[2048,128] 2:cx0[2048,128] 3:W_ih[512,1]
//         4:W_hh[512,128] 5:b_ih[512] 6:b_hh[512] 7:W_mlp[1,128] 8:b_mlp[1]
// output: sigmoid(h_T @ W_mlp^T + b_mlp) -> [2048,1] fp32
//
// Tensor path (base-target PTX, works under compute_103):
//   gates[512,16] = W_fp16[512,128] @ h_fp16[128,16]  per step,
//   via mma.sync.m16n8k16 f16->f32, W fragments register-resident.

#define Bsz 2048
#define Tsz 512
#define Hsz 128
#define ROWS_PER_CTA 16
#define NCTA (Bsz / ROWS_PER_CTA)    // 128
#define NTHREADS 512
#define NPAD 20                      // gates row stride in floats (80B: 16B-aligned, bank-spread)
#define HSTRIDE 48                   // h row stride in bytes (32B data + 16B pad: LDSM conflict-free)

// dynamic SMEM layout (bytes); A-staging (128KB) aliases the whole region at startup
#define OFF_G   0                              // gates f32 [512][NPAD] = 40960
#define OFF_HHI 40960                          // h f16 [128][HSTRIDE] = 6144
#define OFF_X   (OFF_HHI + 6144)               // float [2][16]
#define STAGE_BYTES (512 * 128 * 2)            // 131072
#define DSMEM STAGE_BYTES

typedef unsigned int uint;

__device__ __align__(16) __half g_Whh16[512 * 128];  // fp16 W_hh, original row-major
__device__ float4 g_u[Hsz];   // W_ih per hidden j, gate order i,f,g,o
__device__ float4 g_b[Hsz];   // b_ih + b_hh per hidden j

// ---------------------------------------------------------------------------
__device__ __forceinline__ uint32_t smem_u32(const void* p) {
    uint32_t a;
    asm("{ .reg .u64 t; cvta.to.shared.u64 t, %1; cvt.u32.u64 %0, t; }" : "=r"(a) : "l"(p));
    return a;
}
__device__ __forceinline__ void ldsm_x4(uint32_t* r, uint32_t addr) {
    asm volatile("ldmatrix.sync.aligned.m8n8.x4.shared.b16 {%0,%1,%2,%3}, [%4];"
        : "=r"(r[0]), "=r"(r[1]), "=r"(r[2]), "=r"(r[3]) : "r"(addr));
}
__device__ __forceinline__ void ldsm_x4_t(uint32_t* r, uint32_t addr) {
    asm volatile("ldmatrix.sync.aligned.m8n8.x4.trans.shared.b16 {%0,%1,%2,%3}, [%4];"
        : "=r"(r[0]), "=r"(r[1]), "=r"(r[2]), "=r"(r[3]) : "r"(addr));
}
__device__ __forceinline__ void mma16816(float* d, const uint32_t* a, uint32_t b0, uint32_t b1) {
    asm volatile(
        "mma.sync.aligned.m16n8k16.row.col.f32.f16.f16.f32 "
        "{%0,%1,%2,%3}, {%4,%5,%6,%7}, {%8,%9}, {%0,%1,%2,%3};"
        : "+f"(d[0]), "+f"(d[1]), "+f"(d[2]), "+f"(d[3])
        : "r"(a[0]), "r"(a[1]), "r"(a[2]), "r"(a[3]), "r"(b0), "r"(b1));
}
// MUFU nonlinearities
__device__ __forceinline__ float ex2a(float x) { float r; asm("ex2.approx.f32 %0, %1;" : "=f"(r) : "f"(x)); return r; }
__device__ __forceinline__ float rcpa(float x) { float r; asm("rcp.approx.f32 %0, %1;" : "=f"(r) : "f"(x)); return r; }
__device__ __forceinline__ float fsig(float x)  { return rcpa(1.0f + ex2a(x * -1.4426950408889634f)); }
__device__ __forceinline__ float ftanh(float x) { return fmaf(2.0f, rcpa(1.0f + ex2a(x * -2.8853900817779268f)), -1.0f); }

// ---------------------------------------------------------------------------
// prep: W_hh -> fp16 (row-major, unchanged layout); pack u, fold biases
// ---------------------------------------------------------------------------
__global__ void lstm_prep_kernel(const float* __restrict__ Whh,
                                 const float* __restrict__ Wih,
                                 const float* __restrict__ bih,
                                 const float* __restrict__ bhh) {
    int idx = blockIdx.x * blockDim.x + threadIdx.x;
    if (idx >= 512 * 128) return;
    g_Whh16[idx] = __float2half_rn(Whh[idx]);
    if (idx < Hsz) {
        int j = idx;
        float4 u, b;
        u.x = Wih[0 * Hsz + j]; u.y = Wih[1 * Hsz + j];
        u.z = Wih[2 * Hsz + j]; u.w = Wih[3 * Hsz + j];
        b.x = bih[0 * Hsz + j] + bhh[0 * Hsz + j];
        b.y = bih[1 * Hsz + j] + bhh[1 * Hsz + j];
        b.z = bih[2 * Hsz + j] + bhh[2 * Hsz + j];
        b.w = bih[3 * Hsz + j] + bhh[3 * Hsz + j];
        g_u[j] = u;
        g_b[j] = b;
    }
}

// ---------------------------------------------------------------------------
// main persistent kernel: 128 CTAs x 512 threads (16 warps).
// MMA: warp w owns gate-rows [w*32, w*32+32) (2 m-tiles), all K, N=16.
// Epilogue: thread (j = tid&127, q = tid>>7) owns hidden j, batch cols q*4..+3.
// ---------------------------------------------------------------------------
__global__ __launch_bounds__(NTHREADS, 1)
void lstm_main_kernel(const float* __restrict__ x,
                      const float* __restrict__ hx0,
                      const float* __restrict__ cx0,
                      const float* __restrict__ Wm,
                      const float* __restrict__ bm,
                      float* __restrict__ out) {
    extern __shared__ __align__(16) char dyn[];
    const uint32_t smem_base = smem_u32(dyn);

    const int tid  = threadIdx.x;
    const int w    = tid >> 5;
    const int lane = tid & 31;
    const int j    = tid & 127;
    const int q    = tid >> 7;          // 0..3: batch col group
    const int rowbase = blockIdx.x * ROWS_PER_CTA;

    float* gp  = reinterpret_cast<float*>(dyn + OFF_G);
    float* shX = reinterpret_cast<float*>(dyn + OFF_X);   // [2][16]

    // ---- stage W fp16 into SMEM, then ldmatrix A fragments into registers ----
    {
        const uint4* src = reinterpret_cast<const uint4*>(g_Whh16);
        uint4* dst = reinterpret_cast<uint4*>(dyn);
        for (int i = tid; i < 512 * 128 * 2 / 16; i += NTHREADS) dst[i] = src[i];
    }
    __syncthreads();

    uint32_t Ar[2][8][4];
#pragma unroll
    for (int mt = 0; mt < 2; mt++) {
#pragma unroll
        for (int kt = 0; kt < 8; kt++) {
            int row = w * 32 + mt * 16 + (lane & 15);
            uint32_t byte = (uint32_t)(row * 256 + kt * 32 + (lane >> 4) * 16);
            ldsm_x4(Ar[mt][kt], smem_base + byte);
        }
    }
    __syncthreads();   // A-staging region now free for gates/h/x

    const float4 u = g_u[j];
    const float4 b = g_b[j];

    // ---- init c and h (fp16) ----
    float c[4];
    {
        __half hh[4];
#pragma unroll
        for (int bq = 0; bq < 4; bq++) {
            int row_g = rowbase + q * 4 + bq;
            float h = hx0[row_g * Hsz + j];
            c[bq] = cx0[row_g * Hsz + j];
            hh[bq] = __float2half_rn(h);
        }
        *reinterpret_cast<uint2*>(dyn + OFF_HHI + j * HSTRIDE + q * 8) = *reinterpret_cast<uint2*>(hh);
    }
    if (tid < ROWS_PER_CTA) shX[0 * 16 + tid] = x[(rowbase + tid) * Tsz + 0];
    __syncthreads();

    // B-tile ldmatrix lane addressing (fixed per thread)
    const int sub = lane >> 3, r8 = lane & 7;
    const int brow_off = r8 + (sub & 1) * 8;        // + kt*16
    const int bcol_byte = (sub >> 1) * 16;          // n-col 0 or 8, in bytes
    const uint32_t bhi_base = smem_base + OFF_HHI + brow_off * HSTRIDE + bcol_byte;

    for (int t = 0; t < Tsz; t++) {
        const int cur = t & 1, nxt = cur ^ 1;

        // ---- GEMM: gates = W @ h ----
        float acc[2][2][4];
#pragma unroll
        for (int mt = 0; mt < 2; mt++)
#pragma unroll
            for (int nt = 0; nt < 2; nt++)
#pragma unroll
                for (int e = 0; e < 4; e++) acc[mt][nt][e] = 0.0f;

#pragma unroll
        for (int kt = 0; kt < 8; kt++) {
            uint32_t bh[4];
            ldsm_x4_t(bh, bhi_base + kt * 16 * HSTRIDE);
#pragma unroll
            for (int mt = 0; mt < 2; mt++) {
                mma16816(acc[mt][0], Ar[mt][kt], bh[0], bh[1]);
                mma16816(acc[mt][1], Ar[mt][kt], bh[2], bh[3]);
            }
        }

        // ---- scatter gates to SMEM [512][NPAD] f32 ----
#pragma unroll
        for (int mt = 0; mt < 2; mt++) {
#pragma unroll
            for (int nt = 0; nt < 2; nt++) {
                int row = w * 32 + mt * 16 + (lane >> 2);
                int col = nt * 8 + (lane & 3) * 2;
                *reinterpret_cast<float2*>(&gp[row * NPAD + col])       = make_float2(acc[mt][nt][0], acc[mt][nt][1]);
                *reinterpret_cast<float2*>(&gp[(row + 8) * NPAD + col]) = make_float2(acc[mt][nt][2], acc[mt][nt][3]);
            }
        }
        __syncthreads();

        // ---- epilogue: 4 LSTM cells per thread ----
        {
            float4 G[4];
#pragma unroll
            for (int g = 0; g < 4; g++)
                G[g] = *reinterpret_cast<const float4*>(&gp[(g * 128 + j) * NPAD + q * 4]);
            const float* gi = reinterpret_cast<const float*>(&G[0]);
            const float* gf = reinterpret_cast<const float*>(&G[1]);
            const float* gg = reinterpret_cast<const float*>(&G[2]);
            const float* go = reinterpret_cast<const float*>(&G[3]);

            __half hh[4];
#pragma unroll
            for (int bq = 0; bq < 4; bq++) {
                float xv = shX[cur * 16 + q * 4 + bq];
                float vi = fsig (gi[bq] + fmaf(xv, u.x, b.x));
                float vf = fsig (gf[bq] + fmaf(xv, u.y, b.y));
                float vg = ftanh(gg[bq] + fmaf(xv, u.z, b.z));
                float vo = fsig (go[bq] + fmaf(xv, u.w, b.w));
                c[bq] = fmaf(vf, c[bq], vi * vg);
                float h = vo * ftanh(c[bq]);
                hh[bq] = __float2half_rn(h);
            }
            *reinterpret_cast<uint2*>(dyn + OFF_HHI + j * HSTRIDE + q * 8) = *reinterpret_cast<uint2*>(hh);
        }

        if (tid < ROWS_PER_CTA && (t + 1) < Tsz)
            shX[nxt * 16 + tid] = x[(rowbase + tid) * Tsz + (t + 1)];

        __syncthreads();
    }

    // ---- final h and MLP head ----
    float hfin[4];
    {
        uint2 vh = *reinterpret_cast<uint2*>(dyn + OFF_HHI + j * HSTRIDE + q * 8);
        const __half* ph = reinterpret_cast<const __half*>(&vh);
#pragma unroll
        for (int bq = 0; bq < 4; bq++)
            hfin[bq] = __half2float(ph[bq]);
    }

    float wm = Wm[j];
    float* sf = gp;   // scratch [16][128], reuse gates region
    __syncthreads();
#pragma unroll
    for (int bq = 0; bq < 4; bq++)
        sf[(q * 4 + bq) * Hsz + j] = hfin[bq] * wm;
    __syncthreads();

    if (tid < ROWS_PER_CTA) {
        float s = 0.0f;
#pragma unroll 8
        for (int k = 0; k < Hsz; k++) s += sf[tid * Hsz + k];
        s += bm[0];
        out[rowbase + tid] = fsig(s);
    }
}

// ---------------------------------------------------------------------------
extern "C" void kernel_launch(void* const* d_in, const int* in_sizes, int n_in,
                              void* d_out, int out_size) {
    const float* x    = (const float*)d_in[0];
    const float* hx0  = (const float*)d_in[1];
    const float* cx0  = (const float*)d_in[2];
    const float* Wih  = (const float*)d_in[3];
    const float* Whh  = (const float*)d_in[4];
    const float* bih  = (const float*)d_in[5];
    const float* bhh  = (const float*)d_in[6];
    const float* Wmlp = (const float*)d_in[7];
    const float* bmlp = (const float*)d_in[8];
    float* out = (float*)d_out;

    cudaFuncSetAttribute(lstm_main_kernel,
                         cudaFuncAttributeMaxDynamicSharedMemorySize, DSMEM);

    lstm_prep_kernel<<<(512 * 128 + 255) / 256, 256>>>(Whh, Wih, bih, bhh);
    lstm_main_kernel<<<NCTA, NTHREADS, DSMEM>>>(x, hx0, cx0, Wmlp, bmlp, out);
}

// round 9
// speedup vs baseline: 10.4081x; 1.3720x over previous
#include <cuda_runtime.h>
#include <cuda_fp16.h>
#include <cstdint>

// LSTM_discriminator: B=2048, T=512, H=128, input dim 1.
// inputs: 0:x[2048,512] 1:hx0[2048,128] 2:cx0[2048,128] 3:W_ih[512,1]
//         4:W_hh[512,128] 5:b_ih[512] 6:b_hh[512] 7:W_mlp[1,128] 8:b_mlp[1]
// output: sigmoid(h_T @ W_mlp^T + b_mlp) -> [2048,1] fp32
//
// Transposed tensor path: per step, per CTA (16 batch rows):
//   gates^T[16, 512] = h[16,128] @ W'^T, W' column-permuted (col = w*32 + jl*4 + g)
//   so each warp owns 8 hidden units x 4 gates; epilogue in registers via shfl.

#define Bsz 2048
#define Tsz 512
#define Hsz 128
#define ROWS_PER_CTA 16
#define NCTA (Bsz / ROWS_PER_CTA)    // 128
#define NTHREADS 512
#define HROW 272                     // h row stride bytes (256 data + 16 pad)
#define KSTR 1040                    // staged W'' row stride bytes (1024 data + 16 pad)

// dynamic SMEM (bytes):
//   staging (startup only): W'' [128][KSTR] = 133120
//   persistent (after frag load): hbuf 2x16xHROW=8704 @0 ; shX 2x16 f32 @8704 ; sf 16x128 f32 @8832
#define OFF_H   0
#define OFF_X   8704
#define OFF_SF  8832
#define DSMEM   (128 * KSTR)         // 133120

__device__ __align__(16) __half g_Wperm16[128 * 512];  // [k][col] permuted W_hh fp16
__device__ float2 g_ub[512];                           // per permuted col: {W_ih, b_ih+b_hh}

// ---------------------------------------------------------------------------
__device__ __forceinline__ uint32_t smem_u32(const void* p) {
    uint32_t a;
    asm("{ .reg .u64 t; cvta.to.shared.u64 t, %1; cvt.u32.u64 %0, t; }" : "=r"(a) : "l"(p));
    return a;
}
__device__ __forceinline__ void ldsm_x4(uint32_t* r, uint32_t addr) {
    asm volatile("ldmatrix.sync.aligned.m8n8.x4.shared.b16 {%0,%1,%2,%3}, [%4];"
        : "=r"(r[0]), "=r"(r[1]), "=r"(r[2]), "=r"(r[3]) : "r"(addr));
}
__device__ __forceinline__ void ldsm_x4_t(uint32_t* r, uint32_t addr) {
    asm volatile("ldmatrix.sync.aligned.m8n8.x4.trans.shared.b16 {%0,%1,%2,%3}, [%4];"
        : "=r"(r[0]), "=r"(r[1]), "=r"(r[2]), "=r"(r[3]) : "r"(addr));
}
__device__ __forceinline__ void mma16816(float* d, const uint32_t* a, uint32_t b0, uint32_t b1) {
    asm volatile(
        "mma.sync.aligned.m16n8k16.row.col.f32.f16.f16.f32 "
        "{%0,%1,%2,%3}, {%4,%5,%6,%7}, {%8,%9}, {%0,%1,%2,%3};"
        : "+f"(d[0]), "+f"(d[1]), "+f"(d[2]), "+f"(d[3])
        : "r"(a[0]), "r"(a[1]), "r"(a[2]), "r"(a[3]), "r"(b0), "r"(b1));
}
__device__ __forceinline__ float tanha(float x) {
    float r; asm("tanh.approx.f32 %0, %1;" : "=f"(r) : "f"(x)); return r;
}
__device__ __forceinline__ float fsig(float x)  { return fmaf(0.5f, tanha(0.5f * x), 0.5f); }
__device__ __forceinline__ float ftanh(float x) { return tanha(x); }

// ---------------------------------------------------------------------------
// prep: permuted fp16 W'' [k][col], col = (w<<5)|(jl<<2)|g -> gate row g*128 + w*8 + jl
// ---------------------------------------------------------------------------
__global__ void lstm_prep_kernel(const float* __restrict__ Whh,
                                 const float* __restrict__ Wih,
                                 const float* __restrict__ bih,
                                 const float* __restrict__ bhh) {
    int idx = blockIdx.x * blockDim.x + threadIdx.x;   // 0..65535
    if (idx >= 512 * 128) return;
    int col = idx >> 7;
    int k   = idx & 127;
    int grow = (col & 3) * 128 + (col >> 5) * 8 + ((col >> 2) & 7);
    g_Wperm16[k * 512 + col] = __float2half_rn(Whh[grow * Hsz + k]);
    if (idx < 512) {
        int grow2 = (idx & 3) * 128 + (idx >> 5) * 8 + ((idx >> 2) & 7);
        g_ub[idx] = make_float2(Wih[grow2], bih[grow2] + bhh[grow2]);
    }
}

// ---------------------------------------------------------------------------
// main persistent kernel: 128 CTAs x 512 threads (16 warps).
// Warp w: B = W'' cols [w*32, w*32+32) register-resident; A = h[16,128] per step.
// Thread cell ownership: per n-tile nt, j = w*8 + nt*2 + ((lane>>1)&1),
//   row = (lane&1) ? (lane>>2)+8 : (lane>>2).
// ---------------------------------------------------------------------------
__global__ __launch_bounds__(NTHREADS, 1)
void lstm_main_kernel(const float* __restrict__ x,
                      const float* __restrict__ hx0,
                      const float* __restrict__ cx0,
                      const float* __restrict__ Wm,
                      const float* __restrict__ bm,
                      float* __restrict__ out) {
    extern __shared__ __align__(16) char dyn[];
    const uint32_t smem_base = smem_u32(dyn);

    const int tid  = threadIdx.x;
    const int w    = tid >> 5;
    const int lane = tid & 31;
    const int rowbase = blockIdx.x * ROWS_PER_CTA;

    float* shX = reinterpret_cast<float*>(dyn + OFF_X);   // [2][16]

    // ---- stage permuted W'' into SMEM [128][KSTR] ----
    {
        for (int i = tid; i < 128 * 64; i += NTHREADS) {   // 64 x 16B chunks per row
            int k = i >> 6, ch = i & 63;
            *reinterpret_cast<uint4*>(dyn + k * KSTR + ch * 16) =
                *reinterpret_cast<const uint4*>(g_Wperm16 + k * 512 + ch * 8);
        }
    }
    __syncthreads();

    // ---- load B fragments (validated ldsm.x4.trans addressing) ----
    const int sub = lane >> 3, r8 = lane & 7;
    uint32_t Br[4][8][2];   // [nt][kt][2]
#pragma unroll
    for (int hhalf = 0; hhalf < 2; hhalf++) {
#pragma unroll
        for (int kt = 0; kt < 8; kt++) {
            uint32_t addr = smem_base
                + (uint32_t)((kt * 16 + r8 + (sub & 1) * 8) * KSTR)
                + (uint32_t)((w * 32 + hhalf * 16) * 2) + (uint32_t)((sub >> 1) * 16);
            uint32_t bb[4];
            ldsm_x4_t(bb, addr);
            Br[hhalf * 2 + 0][kt][0] = bb[0]; Br[hhalf * 2 + 0][kt][1] = bb[1];
            Br[hhalf * 2 + 1][kt][0] = bb[2]; Br[hhalf * 2 + 1][kt][1] = bb[3];
        }
    }
    __syncthreads();   // staging region now free -> persistent layout

    // ---- per-thread (u,b) for its 8 gate columns ----
    float2 ub[8];
#pragma unroll
    for (int nt = 0; nt < 4; nt++) {
#pragma unroll
        for (int e = 0; e < 2; e++)
            ub[nt * 2 + e] = g_ub[w * 32 + nt * 8 + (lane & 3) * 2 + e];
    }

    // ---- init c (registers) and h (SMEM fp16 buf 0) ----
    const int r    = lane >> 2;
    const int myrow = (lane & 1) ? (r + 8) : r;
    float c[4];
#pragma unroll
    for (int nt = 0; nt < 4; nt++) {
        int myj = w * 8 + nt * 2 + ((lane >> 1) & 1);
        c[nt] = cx0[(rowbase + myrow) * Hsz + myj];
        float h0 = hx0[(rowbase + myrow) * Hsz + myj];
        *reinterpret_cast<__half*>(dyn + OFF_H + 0 * 16 * HROW + myrow * HROW + myj * 2) =
            __float2half_rn(h0);
    }
    if (tid < ROWS_PER_CTA) shX[0 * 16 + tid] = x[(rowbase + tid) * Tsz + 0];
    __syncthreads();

    // A-operand ldsm base (h rows)
    const uint32_t a_lane_off = (uint32_t)((lane & 15) * HROW + (lane >> 4) * 16);
    const bool ceven = ((lane & 1) == 0);

    for (int t = 0; t < Tsz; t++) {
        const int cur = t & 1, nxt = cur ^ 1;

        // ---- acc init: bias + x*u ----
        float xr0 = shX[cur * 16 + r];
        float xr8 = shX[cur * 16 + r + 8];
        float acc[4][4];
#pragma unroll
        for (int nt = 0; nt < 4; nt++) {
            acc[nt][0] = fmaf(xr0, ub[nt * 2 + 0].x, ub[nt * 2 + 0].y);
            acc[nt][1] = fmaf(xr0, ub[nt * 2 + 1].x, ub[nt * 2 + 1].y);
            acc[nt][2] = fmaf(xr8, ub[nt * 2 + 0].x, ub[nt * 2 + 0].y);
            acc[nt][3] = fmaf(xr8, ub[nt * 2 + 1].x, ub[nt * 2 + 1].y);
        }

        // ---- GEMM: gates^T += h @ W''^T ----
        const uint32_t abase = smem_base + OFF_H + (uint32_t)(cur * 16 * HROW) + a_lane_off;
#pragma unroll
        for (int kt = 0; kt < 8; kt++) {
            uint32_t ah[4];
            ldsm_x4(ah, abase + kt * 32);
#pragma unroll
            for (int nt = 0; nt < 4; nt++)
                mma16816(acc[nt], ah, Br[nt][kt][0], Br[nt][kt][1]);
        }

        // ---- epilogue: pair-exchange + LSTM cell, all in registers ----
#pragma unroll
        for (int nt = 0; nt < 4; nt++) {
            float v0 = ceven ? acc[nt][2] : acc[nt][0];
            float v1 = ceven ? acc[nt][3] : acc[nt][1];
            float rv0 = __shfl_xor_sync(0xFFFFFFFFu, v0, 1);
            float rv1 = __shfl_xor_sync(0xFFFFFFFFu, v1, 1);
            float gi = ceven ? acc[nt][0] : rv0;
            float gf = ceven ? acc[nt][1] : rv1;
            float gg = ceven ? rv0 : acc[nt][2];
            float go = ceven ? rv1 : acc[nt][3];
            float vi = fsig(gi), vf = fsig(gf), vg = ftanh(gg), vo = fsig(go);
            c[nt] = fmaf(vf, c[nt], vi * vg);
            float h = vo * ftanh(c[nt]);
            int myj = w * 8 + nt * 2 + ((lane >> 1) & 1);
            *reinterpret_cast<__half*>(dyn + OFF_H + nxt * 16 * HROW + myrow * HROW + myj * 2) =
                __float2half_rn(h);
        }

        if (tid < ROWS_PER_CTA && (t + 1) < Tsz)
            shX[nxt * 16 + tid] = x[(rowbase + tid) * Tsz + (t + 1)];

        __syncthreads();
    }

    // ---- head: out[row] = sigmoid(sum_j h[row][j]*Wm[j] + bm) ----
    // final h is in buf 0 (Tsz even). thread (j=tid&127, q=tid>>7) covers rows q*4..+3.
    {
        const int j = tid & 127;
        const int q = tid >> 7;
        float wm = Wm[j];
        float* sf = reinterpret_cast<float*>(dyn + OFF_SF);   // [16][128]
#pragma unroll
        for (int bq = 0; bq < 4; bq++) {
            int row = q * 4 + bq;
            float h = __half2float(
                *reinterpret_cast<const __half*>(dyn + OFF_H + 0 * 16 * HROW + row * HROW + j * 2));
            sf[row * Hsz + j] = h * wm;
        }
        __syncthreads();

        if (tid < ROWS_PER_CTA) {
            float s = 0.0f;
#pragma unroll 8
            for (int k = 0; k < Hsz; k++) s += sf[tid * Hsz + k];
            s += bm[0];
            out[rowbase + tid] = fsig(s);
        }
    }
}

// ---------------------------------------------------------------------------
extern "C" void kernel_launch(void* const* d_in, const int* in_sizes, int n_in,
                              void* d_out, int out_size) {
    const float* x    = (const float*)d_in[0];
    const float* hx0  = (const float*)d_in[1];
    const float* cx0  = (const float*)d_in[2];
    const float* Wih  = (const float*)d_in[3];
    const float* Whh  = (const float*)d_in[4];
    const float* bih  = (const float*)d_in[5];
    const float* bhh  = (const float*)d_in[6];
    const float* Wmlp = (const float*)d_in[7];
    const float* bmlp = (const float*)d_in[8];
    float* out = (float*)d_out;

    cudaFuncSetAttribute(lstm_main_kernel,
                         cudaFuncAttributeMaxDynamicSharedMemorySize, DSMEM);

    lstm_prep_kernel<<<(512 * 128 + 255) / 256, 256>>>(Whh, Wih, bih, bhh);
    lstm_main_kernel<<<NCTA, NTHREADS, DSMEM>>>(x, hx0, cx0, Wmlp, bmlp, out);
}

// round 11
// speedup vs baseline: 10.5576x; 1.0144x over previous
#include <cuda_runtime.h>
#include <cuda_fp16.h>
#include <cstdint>

// LSTM_discriminator: B=2048, T=512, H=128, input dim 1.
// inputs: 0:x[2048,512] 1:hx0[2048,128] 2:cx0[2048,128] 3:W_ih[512,1]
//         4:W_hh[512,128] 5:b_ih[512] 6:b_hh[512] 7:W_mlp[1,128] 8:b_mlp[1]
// output: sigmoid(h_T @ W_mlp^T + b_mlp) -> [2048,1] fp32
//
// Transposed tensor path: per step, per CTA (16 batch rows):
//   gates^T[16, 512] = h[16,128] @ W'^T, W' column-permuted (col = w*32 + jl*4 + g)
//   so each warp owns 8 hidden units x 4 gates; epilogue in registers via shfl,
//   nonlinearities via tanh.approx.f16x2 (2 per MUFU op), c kept fp32.

#define Bsz 2048
#define Tsz 512
#define Hsz 128
#define ROWS_PER_CTA 16
#define NCTA (Bsz / ROWS_PER_CTA)    // 128
#define NTHREADS 512
#define HROW 272                     // h row stride bytes (256 data + 16 pad)
#define KSTR 1040                    // staged W'' row stride bytes (1024 data + 16 pad)

// dynamic SMEM (bytes):
//   staging (startup only): W'' [128][KSTR] = 133120
//   persistent (after frag load): hbuf 2x16xHROW=8704 @0 ; shX 2x16 f32 @8704 ; sf 16x128 f32 @8832
#define OFF_H   0
#define OFF_X   8704
#define OFF_SF  8832
#define DSMEM   (128 * KSTR)         // 133120

__device__ __align__(16) __half g_Wperm16[128 * 512];  // [k][col] permuted W_hh fp16
__device__ float2 g_ub[512];                           // per permuted col: {W_ih, b_ih+b_hh}

// ---------------------------------------------------------------------------
__device__ __forceinline__ uint32_t smem_u32(const void* p) {
    uint32_t a;
    asm("{ .reg .u64 t; cvta.to.shared.u64 t, %1; cvt.u32.u64 %0, t; }" : "=r"(a) : "l"(p));
    return a;
}
__device__ __forceinline__ void ldsm_x4(uint32_t* r, uint32_t addr) {
    asm volatile("ldmatrix.sync.aligned.m8n8.x4.shared.b16 {%0,%1,%2,%3}, [%4];"
        : "=r"(r[0]), "=r"(r[1]), "=r"(r[2]), "=r"(r[3]) : "r"(addr));
}
__device__ __forceinline__ void ldsm_x4_t(uint32_t* r, uint32_t addr) {
    asm volatile("ldmatrix.sync.aligned.m8n8.x4.trans.shared.b16 {%0,%1,%2,%3}, [%4];"
        : "=r"(r[0]), "=r"(r[1]), "=r"(r[2]), "=r"(r[3]) : "r"(addr));
}
__device__ __forceinline__ void mma16816(float* d, const uint32_t* a, uint32_t b0, uint32_t b1) {
    asm volatile(
        "mma.sync.aligned.m16n8k16.row.col.f32.f16.f16.f32 "
        "{%0,%1,%2,%3}, {%4,%5,%6,%7}, {%8,%9}, {%0,%1,%2,%3};"
        : "+f"(d[0]), "+f"(d[1]), "+f"(d[2]), "+f"(d[3])
        : "r"(a[0]), "r"(a[1]), "r"(a[2]), "r"(a[3]), "r"(b0), "r"(b1));
}
// f16x2 MUFU helpers
__device__ __forceinline__ uint32_t pack_h2(float lo, float hi) {
    uint32_t r; asm("cvt.rn.f16x2.f32 %0, %1, %2;" : "=r"(r) : "f"(hi), "f"(lo)); return r;
}
__device__ __forceinline__ uint32_t tanh_h2(uint32_t x) {
    uint32_t r; asm("tanh.approx.f16x2 %0, %1;" : "=r"(r) : "r"(x)); return r;
}
__device__ __forceinline__ float lo_f(uint32_t v) { __half2 h = *reinterpret_cast<__half2*>(&v); return __low2float(h); }
__device__ __forceinline__ float hi_f(uint32_t v) { __half2 h = *reinterpret_cast<__half2*>(&v); return __high2float(h); }
__device__ __forceinline__ float tanha(float x) {
    float r; asm("tanh.approx.f32 %0, %1;" : "=f"(r) : "f"(x)); return r;
}
__device__ __forceinline__ float fsig(float x)  { return fmaf(0.5f, tanha(0.5f * x), 0.5f); }

// ---------------------------------------------------------------------------
// prep: permuted fp16 W'' [k][col], col = (w<<5)|(jl<<2)|g -> gate row g*128 + w*8 + jl
// ---------------------------------------------------------------------------
__global__ void lstm_prep_kernel(const float* __restrict__ Whh,
                                 const float* __restrict__ Wih,
                                 const float* __restrict__ bih,
                                 const float* __restrict__ bhh) {
    int idx = blockIdx.x * blockDim.x + threadIdx.x;   // 0..65535
    if (idx >= 512 * 128) return;
    int col = idx >> 7;
    int k   = idx & 127;
    int grow = (col & 3) * 128 + (col >> 5) * 8 + ((col >> 2) & 7);
    g_Wperm16[k * 512 + col] = __float2half_rn(Whh[grow * Hsz + k]);
    if (idx < 512) {
        int grow2 = (idx & 3) * 128 + (idx >> 5) * 8 + ((idx >> 2) & 7);
        g_ub[idx] = make_float2(Wih[grow2], bih[grow2] + bhh[grow2]);
    }
}

// ---------------------------------------------------------------------------
// main persistent kernel: 128 CTAs x 512 threads (16 warps).
// Warp w: B = W'' cols [w*32, w*32+32) register-resident; A = h[16,128] per step.
// ---------------------------------------------------------------------------
__global__ __launch_bounds__(NTHREADS, 1)
void lstm_main_kernel(const float* __restrict__ x,
                      const float* __restrict__ hx0,
                      const float* __restrict__ cx0,
                      const float* __restrict__ Wm,
                      const float* __restrict__ bm,
                      float* __restrict__ out) {
    extern __shared__ __align__(16) char dyn[];
    const uint32_t smem_base = smem_u32(dyn);

    const int tid  = threadIdx.x;
    const int w    = tid >> 5;
    const int lane = tid & 31;
    const int rowbase = blockIdx.x * ROWS_PER_CTA;

    float* shX = reinterpret_cast<float*>(dyn + OFF_X);   // [2][16]

    // ---- stage permuted W'' into SMEM [128][KSTR] ----
    for (int i = tid; i < 128 * 64; i += NTHREADS) {   // 64 x 16B chunks per row
        int k = i >> 6, ch = i & 63;
        *reinterpret_cast<uint4*>(dyn + k * KSTR + ch * 16) =
            *reinterpret_cast<const uint4*>(g_Wperm16 + k * 512 + ch * 8);
    }
    __syncthreads();

    // ---- load B fragments ----
    const int sub = lane >> 3, r8 = lane & 7;
    uint32_t Br[4][8][2];   // [nt][kt][2]
#pragma unroll
    for (int hhalf = 0; hhalf < 2; hhalf++) {
#pragma unroll
        for (int kt = 0; kt < 8; kt++) {
            uint32_t addr = smem_base
                + (uint32_t)((kt * 16 + r8 + (sub & 1) * 8) * KSTR)
                + (uint32_t)((w * 32 + hhalf * 16) * 2) + (uint32_t)((sub >> 1) * 16);
            uint32_t bb[4];
            ldsm_x4_t(bb, addr);
            Br[hhalf * 2 + 0][kt][0] = bb[0]; Br[hhalf * 2 + 0][kt][1] = bb[1];
            Br[hhalf * 2 + 1][kt][0] = bb[2]; Br[hhalf * 2 + 1][kt][1] = bb[3];
        }
    }
    __syncthreads();   // staging region now free -> persistent layout

    // ---- per-thread (u,b) for its 8 gate columns ----
    float2 ub[8];
#pragma unroll
    for (int nt = 0; nt < 4; nt++)
#pragma unroll
        for (int e = 0; e < 2; e++)
            ub[nt * 2 + e] = g_ub[w * 32 + nt * 8 + (lane & 3) * 2 + e];

    // ---- init c (registers) and h (SMEM fp16 buf 0) ----
    const int r     = lane >> 2;
    const int myrow = (lane & 1) ? (r + 8) : r;
    float c[4];
#pragma unroll
    for (int nt = 0; nt < 4; nt++) {
        int myj = w * 8 + nt * 2 + ((lane >> 1) & 1);
        c[nt] = cx0[(rowbase + myrow) * Hsz + myj];
        float h0 = hx0[(rowbase + myrow) * Hsz + myj];
        *reinterpret_cast<__half*>(dyn + OFF_H + 0 * 16 * HROW + myrow * HROW + myj * 2) =
            __float2half_rn(h0);
    }
    if (tid < ROWS_PER_CTA) shX[0 * 16 + tid] = x[(rowbase + tid) * Tsz + 0];
    __syncthreads();

    const uint32_t a_lane_off = (uint32_t)((lane & 15) * HROW + (lane >> 4) * 16);
    const bool ceven = ((lane & 1) == 0);

    for (int t = 0; t < Tsz; t++) {
        const int cur = t & 1, nxt = cur ^ 1;

        // ---- acc init: bias + x*u (all 4 nt) ----
        float xr0 = shX[cur * 16 + r];
        float xr8 = shX[cur * 16 + r + 8];
        float acc[4][4];
#pragma unroll
        for (int nt = 0; nt < 4; nt++) {
            acc[nt][0] = fmaf(xr0, ub[nt * 2 + 0].x, ub[nt * 2 + 0].y);
            acc[nt][1] = fmaf(xr0, ub[nt * 2 + 1].x, ub[nt * 2 + 1].y);
            acc[nt][2] = fmaf(xr8, ub[nt * 2 + 0].x, ub[nt * 2 + 0].y);
            acc[nt][3] = fmaf(xr8, ub[nt * 2 + 1].x, ub[nt * 2 + 1].y);
        }

        const uint32_t abase = smem_base + OFF_H + (uint32_t)(cur * 16 * HROW) + a_lane_off;

        // x prefetch early (latency hides under both passes)
        float xnext = 0.0f;
        if (tid < ROWS_PER_CTA && (t + 1) < Tsz)
            xnext = x[(rowbase + tid) * Tsz + (t + 1)];

        // ================= per nt-pair: GEMM pass then register epilogue ======
#pragma unroll
        for (int p = 0; p < 2; p++) {
            const int na = 2 * p, nb = 2 * p + 1;

            // ---- GEMM pass for this pair ----
#pragma unroll
            for (int kt = 0; kt < 8; kt++) {
                uint32_t ah[4];
                ldsm_x4(ah, abase + kt * 32);
                mma16816(acc[na], ah, Br[na][kt][0], Br[na][kt][1]);
                mma16816(acc[nb], ah, Br[nb][kt][0], Br[nb][kt][1]);
            }

            // ---- epilogue pair: shfl resolve + f16x2 tanh + c/h update ----
            float gi[2], gf[2], gg[2], go[2];
#pragma unroll
            for (int e = 0; e < 2; e++) {
                const int nt = na + e;
                float v0 = ceven ? acc[nt][2] : acc[nt][0];
                float v1 = ceven ? acc[nt][3] : acc[nt][1];
                float rv0 = __shfl_xor_sync(0xFFFFFFFFu, v0, 1);
                float rv1 = __shfl_xor_sync(0xFFFFFFFFu, v1, 1);
                gi[e] = ceven ? acc[nt][0] : rv0;
                gf[e] = ceven ? acc[nt][1] : rv1;
                gg[e] = ceven ? rv0 : acc[nt][2];
                go[e] = ceven ? rv1 : acc[nt][3];
            }
            // 2 cells: 4 gate tanh2 + 1 c tanh2 (c stays fp32)
            uint32_t t1 = tanh_h2(pack_h2(0.5f * gi[0], 0.5f * gf[0]));
            uint32_t t2 = tanh_h2(pack_h2(gg[0],        0.5f * go[0]));
            uint32_t t3 = tanh_h2(pack_h2(0.5f * gi[1], 0.5f * gf[1]));
            uint32_t t4 = tanh_h2(pack_h2(gg[1],        0.5f * go[1]));
            float vi0 = fmaf(0.5f, lo_f(t1), 0.5f), vf0 = fmaf(0.5f, hi_f(t1), 0.5f);
            float vg0 = lo_f(t2),                    vo0 = fmaf(0.5f, hi_f(t2), 0.5f);
            float vi1 = fmaf(0.5f, lo_f(t3), 0.5f), vf1 = fmaf(0.5f, hi_f(t3), 0.5f);
            float vg1 = lo_f(t4),                    vo1 = fmaf(0.5f, hi_f(t4), 0.5f);
            c[na] = fmaf(vf0, c[na], vi0 * vg0);
            c[nb] = fmaf(vf1, c[nb], vi1 * vg1);
            uint32_t t5 = tanh_h2(pack_h2(c[na], c[nb]));
            float h0 = vo0 * lo_f(t5);
            float h1 = vo1 * hi_f(t5);
            int myj0 = w * 8 + na * 2 + ((lane >> 1) & 1);
            int myj1 = w * 8 + nb * 2 + ((lane >> 1) & 1);
            char* hdst = dyn + OFF_H + nxt * 16 * HROW + myrow * HROW;
            *reinterpret_cast<__half*>(hdst + myj0 * 2) = __float2half_rn(h0);
            *reinterpret_cast<__half*>(hdst + myj1 * 2) = __float2half_rn(h1);
        }

        if (tid < ROWS_PER_CTA && (t + 1) < Tsz)
            shX[nxt * 16 + tid] = xnext;

        __syncthreads();
    }

    // ---- head: out[row] = sigmoid(sum_j h[row][j]*Wm[j] + bm) ----
    {
        const int j = tid & 127;
        const int q = tid >> 7;
        float wm = Wm[j];
        float* sf = reinterpret_cast<float*>(dyn + OFF_SF);   // [16][128]
#pragma unroll
        for (int bq = 0; bq < 4; bq++) {
            int row = q * 4 + bq;
            float h = __half2float(
                *reinterpret_cast<const __half*>(dyn + OFF_H + 0 * 16 * HROW + row * HROW + j * 2));
            sf[row * Hsz + j] = h * wm;
        }
        __syncthreads();

        if (tid < ROWS_PER_CTA) {
            float s = 0.0f;
#pragma unroll 8
            for (int k = 0; k < Hsz; k++) s += sf[tid * Hsz + k];
            s += bm[0];
            out[rowbase + tid] = fsig(s);
        }
    }
}

// ---------------------------------------------------------------------------
extern "C" void kernel_launch(void* const* d_in, const int* in_sizes, int n_in,
                              void* d_out, int out_size) {
    const float* x    = (const float*)d_in[0];
    const float* hx0  = (const float*)d_in[1];
    const float* cx0  = (const float*)d_in[2];
    const float* Wih  = (const float*)d_in[3];
    const float* Whh  = (const float*)d_in[4];
    const float* bih  = (const float*)d_in[5];
    const float* bhh  = (const float*)d_in[6];
    const float* Wmlp = (const float*)d_in[7];
    const float* bmlp = (const float*)d_in[8];
    float* out = (float*)d_out;

    cudaFuncSetAttribute(lstm_main_kernel,
                         cudaFuncAttributeMaxDynamicSharedMemorySize, DSMEM);

    lstm_prep_kernel<<<(512 * 128 + 255) / 256, 256>>>(Whh, Wih, bih, bhh);
    lstm_main_kernel<<<NCTA, NTHREADS, DSMEM>>>(x, hx0, cx0, Wmlp, bmlp, out);
}

// round 12
// speedup vs baseline: 12.2750x; 1.1627x over previous
#include <cuda_runtime.h>
#include <cuda_fp16.h>
#include <cstdint>

// LSTM_discriminator: B=2048, T=512, H=128, input dim 1.
// inputs: 0:x[2048,512] 1:hx0[2048,128] 2:cx0[2048,128] 3:W_ih[512,1]
//         4:W_hh[512,128] 5:b_ih[512] 6:b_hh[512] 7:W_mlp[1,128] 8:b_mlp[1]
// output: sigmoid(h_T @ W_mlp^T + b_mlp) -> [2048,1] fp32
//
// Transposed tensor path, gate-major permutation: per step, per CTA (16 rows):
//   gates^T[16,512] = h[16,128] @ W''^T with col = w*32 + g*8 + jl
//   -> each mma n-tile is ONE gate type; a thread's 4 acc sets are the full
//      LSTM cell (i,f,g,o) for the same (row, j-pair). No shuffles.
//   sigma-halving folded into prep weights (i,f,o rows scaled 0.5).

#define Bsz 2048
#define Tsz 512
#define Hsz 128
#define ROWS_PER_CTA 16
#define NCTA (Bsz / ROWS_PER_CTA)    // 128
#define NTHREADS 512
#define HROW 272                     // h row stride bytes (256 data + 16 pad)
#define KSTR 1040                    // staged W'' row stride bytes

#define OFF_H   0
#define OFF_X   8704
#define OFF_SF  8832
#define DSMEM   (128 * KSTR)         // 133120

__device__ __align__(16) __half g_Wperm16[128 * 512];  // [k][col] permuted + scaled W_hh fp16
__device__ float2 g_ub[512];                           // per permuted col: {scaled W_ih, scaled bias}

// ---------------------------------------------------------------------------
__device__ __forceinline__ uint32_t smem_u32(const void* p) {
    uint32_t a;
    asm("{ .reg .u64 t; cvta.to.shared.u64 t, %1; cvt.u32.u64 %0, t; }" : "=r"(a) : "l"(p));
    return a;
}
__device__ __forceinline__ void ldsm_x4(uint32_t* r, uint32_t addr) {
    asm volatile("ldmatrix.sync.aligned.m8n8.x4.shared.b16 {%0,%1,%2,%3}, [%4];"
        : "=r"(r[0]), "=r"(r[1]), "=r"(r[2]), "=r"(r[3]) : "r"(addr));
}
__device__ __forceinline__ void ldsm_x4_t(uint32_t* r, uint32_t addr) {
    asm volatile("ldmatrix.sync.aligned.m8n8.x4.trans.shared.b16 {%0,%1,%2,%3}, [%4];"
        : "=r"(r[0]), "=r"(r[1]), "=r"(r[2]), "=r"(r[3]) : "r"(addr));
}
__device__ __forceinline__ void mma16816(float* d, const uint32_t* a, uint32_t b0, uint32_t b1) {
    asm volatile(
        "mma.sync.aligned.m16n8k16.row.col.f32.f16.f16.f32 "
        "{%0,%1,%2,%3}, {%4,%5,%6,%7}, {%8,%9}, {%0,%1,%2,%3};"
        : "+f"(d[0]), "+f"(d[1]), "+f"(d[2]), "+f"(d[3])
        : "r"(a[0]), "r"(a[1]), "r"(a[2]), "r"(a[3]), "r"(b0), "r"(b1));
}
__device__ __forceinline__ uint32_t pack_h2(float lo, float hi) {
    uint32_t r; asm("cvt.rn.f16x2.f32 %0, %1, %2;" : "=r"(r) : "f"(hi), "f"(lo)); return r;
}
__device__ __forceinline__ __half2 tanh_h2(uint32_t x) {
    uint32_t r; asm("tanh.approx.f16x2 %0, %1;" : "=r"(r) : "r"(x));
    return *reinterpret_cast<__half2*>(&r);
}
__device__ __forceinline__ float tanha(float x) {
    float r; asm("tanh.approx.f32 %0, %1;" : "=f"(r) : "f"(x)); return r;
}
__device__ __forceinline__ float fsig(float x)  { return fmaf(0.5f, tanha(0.5f * x), 0.5f); }

// ---------------------------------------------------------------------------
// prep: permuted+scaled fp16 W'' [k][col], col = w*32 + g*8 + jl -> gate row
// g*128 + w*8 + jl ; rows for gates i,f,o scaled by 0.5 (sigma-halving folded).
// ---------------------------------------------------------------------------
__global__ void lstm_prep_kernel(const float* __restrict__ Whh,
                                 const float* __restrict__ Wih,
                                 const float* __restrict__ bih,
                                 const float* __restrict__ bhh) {
    int idx = blockIdx.x * blockDim.x + threadIdx.x;   // 0..65535
    if (idx >= 512 * 128) return;
    int col = idx >> 7;
    int k   = idx & 127;
    int w2  = col >> 5;
    int g   = (col >> 3) & 3;
    int jl  = col & 7;
    int grow = g * 128 + w2 * 8 + jl;
    float sc = (g == 2) ? 1.0f : 0.5f;
    g_Wperm16[k * 512 + col] = __float2half_rn(sc * Whh[grow * Hsz + k]);
    if (idx < 512) {
        int cw = idx >> 5, cg = (idx >> 3) & 3, cj = idx & 7;
        int gr2 = cg * 128 + cw * 8 + cj;
        float sc2 = (cg == 2) ? 1.0f : 0.5f;
        g_ub[idx] = make_float2(sc2 * Wih[gr2], sc2 * (bih[gr2] + bhh[gr2]));
    }
}

// ---------------------------------------------------------------------------
// main persistent kernel: 128 CTAs x 512 threads (16 warps).
// Warp w: B = W'' cols [w*32, w*32+32) register-resident (nt = gate type);
// thread: rows {r, r+8}, hidden pair j0 = w*8 + (lane&3)*2, j1 = j0+1.
// ---------------------------------------------------------------------------
__global__ __launch_bounds__(NTHREADS, 1)
void lstm_main_kernel(const float* __restrict__ x,
                      const float* __restrict__ hx0,
                      const float* __restrict__ cx0,
                      const float* __restrict__ Wm,
                      const float* __restrict__ bm,
                      float* __restrict__ out) {
    extern __shared__ __align__(16) char dyn[];
    const uint32_t smem_base = smem_u32(dyn);

    const int tid  = threadIdx.x;
    const int w    = tid >> 5;
    const int lane = tid & 31;
    const int rowbase = blockIdx.x * ROWS_PER_CTA;

    float* shX = reinterpret_cast<float*>(dyn + OFF_X);   // [2][16]

    // ---- stage permuted W'' into SMEM [128][KSTR] ----
    for (int i = tid; i < 128 * 64; i += NTHREADS) {
        int k = i >> 6, ch = i & 63;
        *reinterpret_cast<uint4*>(dyn + k * KSTR + ch * 16) =
            *reinterpret_cast<const uint4*>(g_Wperm16 + k * 512 + ch * 8);
    }
    __syncthreads();

    // ---- load B fragments ----
    const int sub = lane >> 3, r8v = lane & 7;
    uint32_t Br[4][8][2];   // [g][kt][2]
#pragma unroll
    for (int hhalf = 0; hhalf < 2; hhalf++) {
#pragma unroll
        for (int kt = 0; kt < 8; kt++) {
            uint32_t addr = smem_base
                + (uint32_t)((kt * 16 + r8v + (sub & 1) * 8) * KSTR)
                + (uint32_t)((w * 32 + hhalf * 16) * 2) + (uint32_t)((sub >> 1) * 16);
            uint32_t bb[4];
            ldsm_x4_t(bb, addr);
            Br[hhalf * 2 + 0][kt][0] = bb[0]; Br[hhalf * 2 + 0][kt][1] = bb[1];
            Br[hhalf * 2 + 1][kt][0] = bb[2]; Br[hhalf * 2 + 1][kt][1] = bb[3];
        }
    }
    __syncthreads();   // staging region now free -> persistent layout

    // ---- per-thread (u,b): gate g, hidden pair {j0,j1} -> ub[g*2+e] ----
    float2 ub[8];
#pragma unroll
    for (int g = 0; g < 4; g++)
#pragma unroll
        for (int e = 0; e < 2; e++)
            ub[g * 2 + e] = g_ub[w * 32 + g * 8 + (lane & 3) * 2 + e];

    // ---- init c (registers) and h (SMEM fp16 buf 0) ----
    const int r  = lane >> 2;
    const int j0 = w * 8 + (lane & 3) * 2;
    float c[4];   // {r:j0, r:j1, r+8:j0, r+8:j1}
    {
        c[0] = cx0[(rowbase + r) * Hsz + j0];
        c[1] = cx0[(rowbase + r) * Hsz + j0 + 1];
        c[2] = cx0[(rowbase + r + 8) * Hsz + j0];
        c[3] = cx0[(rowbase + r + 8) * Hsz + j0 + 1];
        float h00 = hx0[(rowbase + r) * Hsz + j0];
        float h01 = hx0[(rowbase + r) * Hsz + j0 + 1];
        float h10 = hx0[(rowbase + r + 8) * Hsz + j0];
        float h11 = hx0[(rowbase + r + 8) * Hsz + j0 + 1];
        *reinterpret_cast<uint32_t*>(dyn + OFF_H + r * HROW + j0 * 2) = pack_h2(h00, h01);
        *reinterpret_cast<uint32_t*>(dyn + OFF_H + (r + 8) * HROW + j0 * 2) = pack_h2(h10, h11);
    }
    if (tid < ROWS_PER_CTA) shX[0 * 16 + tid] = x[(rowbase + tid) * Tsz + 0];
    __syncthreads();

    const uint32_t a_lane_off = (uint32_t)((lane & 15) * HROW + (lane >> 4) * 16);
    const __half2 h05 = __half2half2(__float2half(0.5f));

    for (int t = 0; t < Tsz; t++) {
        const int cur = t & 1, nxt = cur ^ 1;

        // ---- acc init: scaled bias + x*u ----
        float xr0 = shX[cur * 16 + r];
        float xr8 = shX[cur * 16 + r + 8];
        float acc[4][4];
#pragma unroll
        for (int g = 0; g < 4; g++) {
            acc[g][0] = fmaf(xr0, ub[g * 2 + 0].x, ub[g * 2 + 0].y);
            acc[g][1] = fmaf(xr0, ub[g * 2 + 1].x, ub[g * 2 + 1].y);
            acc[g][2] = fmaf(xr8, ub[g * 2 + 0].x, ub[g * 2 + 0].y);
            acc[g][3] = fmaf(xr8, ub[g * 2 + 1].x, ub[g * 2 + 1].y);
        }

        // x prefetch early
        float xnext = 0.0f;
        if (tid < ROWS_PER_CTA && (t + 1) < Tsz)
            xnext = x[(rowbase + tid) * Tsz + (t + 1)];

        // ---- GEMM: single pass, 4-acc ILP ----
        const uint32_t abase = smem_base + OFF_H + (uint32_t)(cur * 16 * HROW) + a_lane_off;
#pragma unroll
        for (int kt = 0; kt < 8; kt++) {
            uint32_t ah[4];
            ldsm_x4(ah, abase + kt * 32);
#pragma unroll
            for (int g = 0; g < 4; g++)
                mma16816(acc[g], ah, Br[g][kt][0], Br[g][kt][1]);
        }

        // ---- epilogue: full cell in registers, h2 SIMD over the j-pair ----
#pragma unroll
        for (int m = 0; m < 2; m++) {
            // gates for (row r or r+8), j0/j1 pair; i,f,o pre-halved by prep
            __half2 tI = tanh_h2(pack_h2(acc[0][2 * m], acc[0][2 * m + 1]));
            __half2 tF = tanh_h2(pack_h2(acc[1][2 * m], acc[1][2 * m + 1]));
            __half2 tG = tanh_h2(pack_h2(acc[2][2 * m], acc[2][2 * m + 1]));
            __half2 tO = tanh_h2(pack_h2(acc[3][2 * m], acc[3][2 * m + 1]));
            __half2 sI = __hfma2(tI, h05, h05);
            __half2 sF = __hfma2(tF, h05, h05);
            __half2 sO = __hfma2(tO, h05, h05);
            __half2 ig = __hmul2(sI, tG);
            float2 igf = __half22float2(ig);
            float2 vff = __half22float2(sF);
            c[2 * m + 0] = fmaf(vff.x, c[2 * m + 0], igf.x);
            c[2 * m + 1] = fmaf(vff.y, c[2 * m + 1], igf.y);
            __half2 tC = tanh_h2(pack_h2(c[2 * m + 0], c[2 * m + 1]));
            __half2 h2v = __hmul2(sO, tC);
            int row = (m == 0) ? r : (r + 8);
            *reinterpret_cast<__half2*>(dyn + OFF_H + nxt * 16 * HROW + row * HROW + j0 * 2) = h2v;
        }

        if (tid < ROWS_PER_CTA && (t + 1) < Tsz)
            shX[nxt * 16 + tid] = xnext;

        __syncthreads();
    }

    // ---- head: out[row] = sigmoid(sum_j h[row][j]*Wm[j] + bm) ----
    {
        const int j = tid & 127;
        const int q = tid >> 7;
        float wm = Wm[j];
        float* sf = reinterpret_cast<float*>(dyn + OFF_SF);   // [16][128]
#pragma unroll
        for (int bq = 0; bq < 4; bq++) {
            int row = q * 4 + bq;
            float h = __half2float(
                *reinterpret_cast<const __half*>(dyn + OFF_H + 0 * 16 * HROW + row * HROW + j * 2));
            sf[row * Hsz + j] = h * wm;
        }
        __syncthreads();

        if (tid < ROWS_PER_CTA) {
            float s = 0.0f;
#pragma unroll 8
            for (int k = 0; k < Hsz; k++) s += sf[tid * Hsz + k];
            s += bm[0];
            out[rowbase + tid] = fsig(s);
        }
    }
}

// ---------------------------------------------------------------------------
extern "C" void kernel_launch(void* const* d_in, const int* in_sizes, int n_in,
                              void* d_out, int out_size) {
    const float* x    = (const float*)d_in[0];
    const float* hx0  = (const float*)d_in[1];
    const float* cx0  = (const float*)d_in[2];
    const float* Wih  = (const float*)d_in[3];
    const float* Whh  = (const float*)d_in[4];
    const float* bih  = (const float*)d_in[5];
    const float* bhh  = (const float*)d_in[6];
    const float* Wmlp = (const float*)d_in[7];
    const float* bmlp = (const float*)d_in[8];
    float* out = (float*)d_out;

    cudaFuncSetAttribute(lstm_main_kernel,
                         cudaFuncAttributeMaxDynamicSharedMemorySize, DSMEM);

    lstm_prep_kernel<<<(512 * 128 + 255) / 256, 256>>>(Whh, Wih, bih, bhh);
    lstm_main_kernel<<<NCTA, NTHREADS, DSMEM>>>(x, hx0, cx0, Wmlp, bmlp, out);
}